// round 1
// baseline (speedup 1.0000x reference)
#include <cuda_runtime.h>
#include <cuda_bf16.h>
#include <math.h>

// Problem constants (fixed by setup_inputs)
#define B_   2
#define L_   2048
#define D_   768
#define H_   12
#define HD_  64
#define ML_  (B_ * L_)          // 4096 rows
#define QKV_N (3 * D_)          // 2304
static const float SCALE_ = 0.125f;  // 64^-0.5

// Scratch (device globals — no allocation allowed)
__device__ float g_qkv[(size_t)ML_ * QKV_N];   // [4096, 2304]
__device__ float g_att[(size_t)ML_ * D_];      // [4096, 768]

// ---------------------------------------------------------------------------
// SGEMM with bias: C[M,N] = A[M,K] @ B[K,N] + bias[N]
// BM=BN=128, BK=8, 256 threads, 8x8 per thread. M%128==0, N%128==0, K%8==0.
// ---------------------------------------------------------------------------
__global__ __launch_bounds__(256)
void sgemm_bias_kernel(const float* __restrict__ A, const float* __restrict__ Bm,
                       const float* __restrict__ bias, float* __restrict__ C,
                       int M, int N, int K)
{
    __shared__ float As[8][128];
    __shared__ float Bs[8][128];

    const int tid = threadIdx.x;
    const int tx = tid % 16;
    const int ty = tid / 16;
    const int row0 = blockIdx.y * 128;
    const int col0 = blockIdx.x * 128;

    // load mapping
    const int aRow = tid >> 1;          // 0..127
    const int aCol = (tid & 1) * 4;     // 0 or 4
    const int bRow = tid >> 5;          // 0..7
    const int bCol = (tid & 31) * 4;    // 0..124

    float acc[8][8];
#pragma unroll
    for (int i = 0; i < 8; i++)
#pragma unroll
        for (int j = 0; j < 8; j++) acc[i][j] = 0.0f;

    for (int k0 = 0; k0 < K; k0 += 8) {
        float4 a = *reinterpret_cast<const float4*>(A + (size_t)(row0 + aRow) * K + k0 + aCol);
        As[aCol + 0][aRow] = a.x;
        As[aCol + 1][aRow] = a.y;
        As[aCol + 2][aRow] = a.z;
        As[aCol + 3][aRow] = a.w;
        float4 b = *reinterpret_cast<const float4*>(Bm + (size_t)(k0 + bRow) * N + col0 + bCol);
        *reinterpret_cast<float4*>(&Bs[bRow][bCol]) = b;
        __syncthreads();

#pragma unroll
        for (int kk = 0; kk < 8; kk++) {
            float af[8], bf[8];
            *reinterpret_cast<float4*>(&af[0]) = *reinterpret_cast<const float4*>(&As[kk][ty * 8]);
            *reinterpret_cast<float4*>(&af[4]) = *reinterpret_cast<const float4*>(&As[kk][ty * 8 + 4]);
            *reinterpret_cast<float4*>(&bf[0]) = *reinterpret_cast<const float4*>(&Bs[kk][tx * 8]);
            *reinterpret_cast<float4*>(&bf[4]) = *reinterpret_cast<const float4*>(&Bs[kk][tx * 8 + 4]);
#pragma unroll
            for (int i = 0; i < 8; i++)
#pragma unroll
                for (int j = 0; j < 8; j++)
                    acc[i][j] = fmaf(af[i], bf[j], acc[i][j]);
        }
        __syncthreads();
    }

#pragma unroll
    for (int i = 0; i < 8; i++) {
        const int r = row0 + ty * 8 + i;
#pragma unroll
        for (int j = 0; j < 8; j++) {
            const int c = col0 + tx * 8 + j;
            C[(size_t)r * N + c] = acc[i][j] + bias[c];
        }
    }
}

// ---------------------------------------------------------------------------
// Flash-style attention. One CTA per (qtile=64 rows, head, batch).
// Threads: 256 (16x16). Per thread: 4x4 of the 64x64 S tile, 4x4 of O.
// Shared (dynamic): Qs, Ks, Vs, Ps each [64][65] floats = 66560 B.
// ---------------------------------------------------------------------------
#define PAD 65
#define ATT_SMEM_BYTES (4 * 64 * PAD * 4)

__global__ __launch_bounds__(256)
void attn_kernel(const float* __restrict__ qkv, float* __restrict__ out)
{
    extern __shared__ float sm[];
    float* Qs = sm;
    float* Ks = Qs + 64 * PAD;
    float* Vs = Ks + 64 * PAD;
    float* Ps = Vs + 64 * PAD;

    const int tid = threadIdx.x;
    const int tx = tid % 16;
    const int ty = tid / 16;
    const int qblk = blockIdx.x;      // 0..31
    const int h    = blockIdx.y;      // 0..11
    const int b    = blockIdx.z;      // 0..1

    const size_t rowStride = QKV_N;
    const size_t baseQ = ((size_t)b * L_ + qblk * 64) * rowStride + h * HD_;
    const size_t baseK = (size_t)b * L_ * rowStride + D_ + h * HD_;
    const size_t baseV = (size_t)b * L_ * rowStride + 2 * D_ + h * HD_;

    // Load Q tile: 64 rows x 64 floats
    for (int e = tid; e < 64 * 16; e += 256) {
        const int r  = e >> 4;
        const int d4 = (e & 15) * 4;
        float4 v = *reinterpret_cast<const float4*>(qkv + baseQ + (size_t)r * rowStride + d4);
        Qs[r * PAD + d4 + 0] = v.x;
        Qs[r * PAD + d4 + 1] = v.y;
        Qs[r * PAD + d4 + 2] = v.z;
        Qs[r * PAD + d4 + 3] = v.w;
    }

    float O[4][4];
    float m[4], l[4];
#pragma unroll
    for (int r = 0; r < 4; r++) {
        m[r] = -INFINITY; l[r] = 0.0f;
#pragma unroll
        for (int c = 0; c < 4; c++) O[r][c] = 0.0f;
    }

    __syncthreads();

    for (int j0 = 0; j0 < L_; j0 += 64) {
        // Load K and V blocks
        for (int e = tid; e < 64 * 16; e += 256) {
            const int r  = e >> 4;
            const int d4 = (e & 15) * 4;
            float4 kv = *reinterpret_cast<const float4*>(qkv + baseK + (size_t)(j0 + r) * rowStride + d4);
            Ks[r * PAD + d4 + 0] = kv.x;
            Ks[r * PAD + d4 + 1] = kv.y;
            Ks[r * PAD + d4 + 2] = kv.z;
            Ks[r * PAD + d4 + 3] = kv.w;
            float4 vv = *reinterpret_cast<const float4*>(qkv + baseV + (size_t)(j0 + r) * rowStride + d4);
            Vs[r * PAD + d4 + 0] = vv.x;
            Vs[r * PAD + d4 + 1] = vv.y;
            Vs[r * PAD + d4 + 2] = vv.z;
            Vs[r * PAD + d4 + 3] = vv.w;
        }
        __syncthreads();

        // S = Q K^T * scale  (4x4 per thread)
        float s[4][4];
#pragma unroll
        for (int r = 0; r < 4; r++)
#pragma unroll
            for (int c = 0; c < 4; c++) s[r][c] = 0.0f;

#pragma unroll 8
        for (int kk = 0; kk < 64; kk++) {
            float qf[4], kf[4];
#pragma unroll
            for (int r = 0; r < 4; r++) qf[r] = Qs[(ty * 4 + r) * PAD + kk];
#pragma unroll
            for (int c = 0; c < 4; c++) kf[c] = Ks[(tx * 4 + c) * PAD + kk];
#pragma unroll
            for (int r = 0; r < 4; r++)
#pragma unroll
                for (int c = 0; c < 4; c++)
                    s[r][c] = fmaf(qf[r], kf[c], s[r][c]);
        }

        // Online softmax per row (reduce across the 16 tx-lanes; lane = (ty&1)*16+tx,
        // xor masks <16 stay within the same 16-lane half-warp)
#pragma unroll
        for (int r = 0; r < 4; r++) {
            float mx = -INFINITY;
#pragma unroll
            for (int c = 0; c < 4; c++) {
                s[r][c] *= SCALE_;
                mx = fmaxf(mx, s[r][c]);
            }
#pragma unroll
            for (int o = 8; o >= 1; o >>= 1)
                mx = fmaxf(mx, __shfl_xor_sync(0xffffffffu, mx, o));

            const float m_new = fmaxf(m[r], mx);
            const float corr  = __expf(m[r] - m_new);
            float rs = 0.0f;
#pragma unroll
            for (int c = 0; c < 4; c++) {
                const float p = __expf(s[r][c] - m_new);
                s[r][c] = p;
                rs += p;
            }
#pragma unroll
            for (int o = 8; o >= 1; o >>= 1)
                rs += __shfl_xor_sync(0xffffffffu, rs, o);

            l[r] = l[r] * corr + rs;
            m[r] = m_new;
#pragma unroll
            for (int c = 0; c < 4; c++) O[r][c] *= corr;
        }

        // Stage P tile to shared
#pragma unroll
        for (int r = 0; r < 4; r++)
#pragma unroll
            for (int c = 0; c < 4; c++)
                Ps[(ty * 4 + r) * PAD + tx * 4 + c] = s[r][c];
        __syncthreads();

        // O += P @ V
#pragma unroll 8
        for (int j = 0; j < 64; j++) {
            float pf[4], vf[4];
#pragma unroll
            for (int r = 0; r < 4; r++) pf[r] = Ps[(ty * 4 + r) * PAD + j];
#pragma unroll
            for (int c = 0; c < 4; c++) vf[c] = Vs[j * PAD + tx * 4 + c];
#pragma unroll
            for (int r = 0; r < 4; r++)
#pragma unroll
                for (int c = 0; c < 4; c++)
                    O[r][c] = fmaf(pf[r], vf[c], O[r][c]);
        }
        __syncthreads();
    }

    // Normalize + write to g_att laid out as [B, L, D] with head offset
#pragma unroll
    for (int r = 0; r < 4; r++) {
        const float inv_l = 1.0f / l[r];
        const size_t row = (size_t)b * L_ + qblk * 64 + ty * 4 + r;
#pragma unroll
        for (int c = 0; c < 4; c++)
            out[row * D_ + h * HD_ + tx * 4 + c] = O[r][c] * inv_l;
    }
}

// ---------------------------------------------------------------------------
// Host launcher
// ---------------------------------------------------------------------------
extern "C" void kernel_launch(void* const* d_in, const int* in_sizes, int n_in,
                              void* d_out, int out_size)
{
    const float* x     = (const float*)d_in[0];   // [2, 2048, 768]
    const float* Wqkv  = (const float*)d_in[1];   // [768, 2304]
    const float* bqkv  = (const float*)d_in[2];   // [2304]
    const float* Wproj = (const float*)d_in[3];   // [768, 768]
    const float* bproj = (const float*)d_in[4];   // [768]
    float* out = (float*)d_out;                   // [2, 2048, 768]

    float* qkv; float* att;
    cudaGetSymbolAddress((void**)&qkv, g_qkv);
    cudaGetSymbolAddress((void**)&att, g_att);

    // 1) QKV projection: [4096,768] @ [768,2304] + bqkv
    {
        dim3 grid(QKV_N / 128, ML_ / 128);
        sgemm_bias_kernel<<<grid, 256>>>(x, Wqkv, bqkv, qkv, ML_, QKV_N, D_);
    }

    // 2) Attention
    {
        static bool attr_set = false;
        if (!attr_set) {
            cudaFuncSetAttribute(attn_kernel,
                                 cudaFuncAttributeMaxDynamicSharedMemorySize,
                                 ATT_SMEM_BYTES);
            attr_set = true;
        }
        dim3 grid(L_ / 64, H_, B_);
        attn_kernel<<<grid, 256, ATT_SMEM_BYTES>>>(qkv, att);
    }

    // 3) Output projection: [4096,768] @ [768,768] + bproj
    {
        dim3 grid(D_ / 128, ML_ / 128);
        sgemm_bias_kernel<<<grid, 256>>>(att, Wproj, bproj, out, ML_, D_, D_);
    }
}

// round 2
// speedup vs baseline: 3.5062x; 3.5062x over previous
#include <cuda_runtime.h>
#include <math.h>

// Problem constants
#define B_   2
#define L_   2048
#define D_   768
#define H_   12
#define HD_  64
#define ML_  (B_ * L_)          // 4096
#define QKV_N (3 * D_)          // 2304
#define SCALE_ 0.125f

// Scratch (device globals — no allocation allowed)
__device__ float g_qkv[(size_t)ML_ * QKV_N];   // [4096, 2304]
__device__ float g_att[(size_t)ML_ * D_];      // [4096, 768]

// ---------------------------------------------------------------------------
// tf32 helpers
// ---------------------------------------------------------------------------
__device__ __forceinline__ unsigned f2t(float x) {
    unsigned u;
    asm("cvt.rna.tf32.f32 %0, %1;" : "=r"(u) : "f"(x));
    return u;
}

__device__ __forceinline__ void mma8(float* c,
                                     unsigned a0, unsigned a1, unsigned a2, unsigned a3,
                                     unsigned b0, unsigned b1) {
    asm volatile(
        "mma.sync.aligned.m16n8k8.row.col.f32.tf32.tf32.f32 "
        "{%0,%1,%2,%3},{%4,%5,%6,%7},{%8,%9},{%0,%1,%2,%3};"
        : "+f"(c[0]), "+f"(c[1]), "+f"(c[2]), "+f"(c[3])
        : "r"(a0), "r"(a1), "r"(a2), "r"(a3), "r"(b0), "r"(b1));
}

// ---------------------------------------------------------------------------
// tf32 GEMM + bias: C[M,N] = A[M,K] @ B[K,N] + bias.
// 128x128x32 tiles, 256 threads (8 warps, 2x4), warp = 64x32, mma m16n8k8.
// Requires M%128==0, N%128==0, K%32==0.
// ---------------------------------------------------------------------------
#define APAD 4   // As stride 36 -> frag reads conflict-free
#define BPAD 8   // Bs stride 136 -> frag reads conflict-free

__global__ __launch_bounds__(256)
void gemm_tf32(const float* __restrict__ A, const float* __restrict__ Bm,
               const float* __restrict__ bias, float* __restrict__ C,
               int M, int N, int K)
{
    __shared__ float As[128][32 + APAD];
    __shared__ float Bs[32][128 + BPAD];

    const int tid  = threadIdx.x;
    const int wid  = tid >> 5;
    const int lane = tid & 31;
    const int g    = lane >> 2;   // group id 0..7
    const int tig  = lane & 3;    // thread-in-group 0..3
    const int wm   = wid >> 2;    // 0..1  -> 64-row slab
    const int wn   = wid & 3;     // 0..3  -> 32-col slab
    const int row0 = blockIdx.y * 128;
    const int col0 = blockIdx.x * 128;

    float acc[4][4][4];
#pragma unroll
    for (int mt = 0; mt < 4; mt++)
#pragma unroll
        for (int nt = 0; nt < 4; nt++)
#pragma unroll
            for (int i = 0; i < 4; i++) acc[mt][nt][i] = 0.0f;

    for (int k0 = 0; k0 < K; k0 += 32) {
        // A tile: 128x32 (tf32-rounded)
#pragma unroll
        for (int i = 0; i < 4; i++) {
            const int r = (tid >> 3) + i * 32;
            const int c = (tid & 7) * 4;
            float4 v = *reinterpret_cast<const float4*>(A + (size_t)(row0 + r) * K + k0 + c);
            As[r][c + 0] = __uint_as_float(f2t(v.x));
            As[r][c + 1] = __uint_as_float(f2t(v.y));
            As[r][c + 2] = __uint_as_float(f2t(v.z));
            As[r][c + 3] = __uint_as_float(f2t(v.w));
        }
        // B tile: 32x128
#pragma unroll
        for (int i = 0; i < 4; i++) {
            const int r = (tid >> 5) + i * 8;
            const int c = (tid & 31) * 4;
            float4 v = *reinterpret_cast<const float4*>(Bm + (size_t)(k0 + r) * N + col0 + c);
            Bs[r][c + 0] = __uint_as_float(f2t(v.x));
            Bs[r][c + 1] = __uint_as_float(f2t(v.y));
            Bs[r][c + 2] = __uint_as_float(f2t(v.z));
            Bs[r][c + 3] = __uint_as_float(f2t(v.w));
        }
        __syncthreads();

#pragma unroll
        for (int kk = 0; kk < 4; kk++) {
            unsigned af[4][4], bf[4][2];
#pragma unroll
            for (int mt = 0; mt < 4; mt++) {
                const int r = wm * 64 + mt * 16 + g;
                af[mt][0] = __float_as_uint(As[r    ][kk * 8 + tig]);
                af[mt][1] = __float_as_uint(As[r + 8][kk * 8 + tig]);
                af[mt][2] = __float_as_uint(As[r    ][kk * 8 + tig + 4]);
                af[mt][3] = __float_as_uint(As[r + 8][kk * 8 + tig + 4]);
            }
#pragma unroll
            for (int nt = 0; nt < 4; nt++) {
                const int c = wn * 32 + nt * 8 + g;
                bf[nt][0] = __float_as_uint(Bs[kk * 8 + tig    ][c]);
                bf[nt][1] = __float_as_uint(Bs[kk * 8 + tig + 4][c]);
            }
#pragma unroll
            for (int mt = 0; mt < 4; mt++)
#pragma unroll
                for (int nt = 0; nt < 4; nt++)
                    mma8(acc[mt][nt], af[mt][0], af[mt][1], af[mt][2], af[mt][3],
                         bf[nt][0], bf[nt][1]);
        }
        __syncthreads();
    }

    // Epilogue: bias + store (float2 per fragment row)
#pragma unroll
    for (int mt = 0; mt < 4; mt++) {
        const int r = row0 + wm * 64 + mt * 16 + g;
#pragma unroll
        for (int nt = 0; nt < 4; nt++) {
            const int c = col0 + wn * 32 + nt * 8 + tig * 2;
            const float b0v = bias[c], b1v = bias[c + 1];
            float2 lo = make_float2(acc[mt][nt][0] + b0v, acc[mt][nt][1] + b1v);
            float2 hi = make_float2(acc[mt][nt][2] + b0v, acc[mt][nt][3] + b1v);
            *reinterpret_cast<float2*>(C + (size_t)r * N + c)       = lo;
            *reinterpret_cast<float2*>(C + (size_t)(r + 8) * N + c) = hi;
        }
    }
}

// ---------------------------------------------------------------------------
// Flash attention, tf32 MMA. CTA = (64 q-rows, head, batch), 4 warps.
// Warp owns 16 q-rows: S (16x64) and O (16x64) in m16n8 C-fragments.
// K/V staged in smem; P round-trips through warp-private smem.
// ---------------------------------------------------------------------------
#define KSTR 68
#define VSTR 72
#define PSTR 68
#define ATT_SMEM ((64 * KSTR + 64 * VSTR + 4 * 16 * PSTR) * 4)

__global__ __launch_bounds__(128)
void attn_tf32(const float* __restrict__ qkv, float* __restrict__ out)
{
    extern __shared__ float sm[];
    float* Ks = sm;
    float* Vs = Ks + 64 * KSTR;
    float* Ps = Vs + 64 * VSTR;

    const int tid  = threadIdx.x;
    const int wid  = tid >> 5;
    const int lane = tid & 31;
    const int g    = lane >> 2;
    const int tig  = lane & 3;
    const int qblk = blockIdx.x;
    const int h    = blockIdx.y;
    const int b    = blockIdx.z;

    const size_t rs    = QKV_N;
    const size_t baseQ = ((size_t)b * L_ + qblk * 64) * rs + h * HD_;
    const size_t baseK = (size_t)b * L_ * rs + D_ + h * HD_;
    const size_t baseV = (size_t)b * L_ * rs + 2 * D_ + h * HD_;

    // Q fragments (pre-scaled, tf32-rounded), register-resident
    unsigned qa[8][4];
    {
        const float* q0 = qkv + baseQ + (size_t)(wid * 16 + g) * rs;
        const float* q8 = q0 + 8 * rs;
#pragma unroll
        for (int kk = 0; kk < 8; kk++) {
            const int c = kk * 8 + tig;
            qa[kk][0] = f2t(q0[c]     * SCALE_);
            qa[kk][1] = f2t(q8[c]     * SCALE_);
            qa[kk][2] = f2t(q0[c + 4] * SCALE_);
            qa[kk][3] = f2t(q8[c + 4] * SCALE_);
        }
    }

    float oc[8][4];
#pragma unroll
    for (int nt = 0; nt < 8; nt++)
#pragma unroll
        for (int i = 0; i < 4; i++) oc[nt][i] = 0.0f;
    float m0 = -INFINITY, m1 = -INFINITY, l0 = 0.0f, l1 = 0.0f;

    float* Pw = Ps + wid * 16 * PSTR;

    for (int j0 = 0; j0 < L_; j0 += 64) {
        // Stage K/V tile (tf32-rounded)
#pragma unroll
        for (int e = tid; e < 64 * 16; e += 128) {
            const int r = e >> 4;
            const int c = (e & 15) * 4;
            float4 kv = *reinterpret_cast<const float4*>(qkv + baseK + (size_t)(j0 + r) * rs + c);
            float4 ks = make_float4(__uint_as_float(f2t(kv.x)), __uint_as_float(f2t(kv.y)),
                                    __uint_as_float(f2t(kv.z)), __uint_as_float(f2t(kv.w)));
            *reinterpret_cast<float4*>(&Ks[r * KSTR + c]) = ks;
            float4 vv = *reinterpret_cast<const float4*>(qkv + baseV + (size_t)(j0 + r) * rs + c);
            float4 vs = make_float4(__uint_as_float(f2t(vv.x)), __uint_as_float(f2t(vv.y)),
                                    __uint_as_float(f2t(vv.z)), __uint_as_float(f2t(vv.w)));
            *reinterpret_cast<float4*>(&Vs[r * VSTR + c]) = vs;
        }
        __syncthreads();

        // S = (Q*scale) @ K^T : 8 n-tiles of m16n8
        float s[8][4];
#pragma unroll
        for (int nt = 0; nt < 8; nt++)
#pragma unroll
            for (int i = 0; i < 4; i++) s[nt][i] = 0.0f;

#pragma unroll
        for (int kk = 0; kk < 8; kk++) {
#pragma unroll
            for (int nt = 0; nt < 8; nt++) {
                const unsigned b0 = __float_as_uint(Ks[(nt * 8 + g) * KSTR + kk * 8 + tig]);
                const unsigned b1 = __float_as_uint(Ks[(nt * 8 + g) * KSTR + kk * 8 + tig + 4]);
                mma8(s[nt], qa[kk][0], qa[kk][1], qa[kk][2], qa[kk][3], b0, b1);
            }
        }

        // Online softmax (rows g and g+8; reduce over quad lanes)
        float mx0 = -INFINITY, mx1 = -INFINITY;
#pragma unroll
        for (int nt = 0; nt < 8; nt++) {
            mx0 = fmaxf(mx0, fmaxf(s[nt][0], s[nt][1]));
            mx1 = fmaxf(mx1, fmaxf(s[nt][2], s[nt][3]));
        }
        mx0 = fmaxf(mx0, __shfl_xor_sync(0xffffffffu, mx0, 1));
        mx0 = fmaxf(mx0, __shfl_xor_sync(0xffffffffu, mx0, 2));
        mx1 = fmaxf(mx1, __shfl_xor_sync(0xffffffffu, mx1, 1));
        mx1 = fmaxf(mx1, __shfl_xor_sync(0xffffffffu, mx1, 2));

        const float mn0 = fmaxf(m0, mx0);
        const float mn1 = fmaxf(m1, mx1);
        const float corr0 = __expf(m0 - mn0);
        const float corr1 = __expf(m1 - mn1);
        m0 = mn0; m1 = mn1;

        float sum0 = 0.0f, sum1 = 0.0f;
#pragma unroll
        for (int nt = 0; nt < 8; nt++) {
            s[nt][0] = __expf(s[nt][0] - mn0); sum0 += s[nt][0];
            s[nt][1] = __expf(s[nt][1] - mn0); sum0 += s[nt][1];
            s[nt][2] = __expf(s[nt][2] - mn1); sum1 += s[nt][2];
            s[nt][3] = __expf(s[nt][3] - mn1); sum1 += s[nt][3];
        }
        sum0 += __shfl_xor_sync(0xffffffffu, sum0, 1);
        sum0 += __shfl_xor_sync(0xffffffffu, sum0, 2);
        sum1 += __shfl_xor_sync(0xffffffffu, sum1, 1);
        sum1 += __shfl_xor_sync(0xffffffffu, sum1, 2);

        l0 = l0 * corr0 + sum0;
        l1 = l1 * corr1 + sum1;
#pragma unroll
        for (int nt = 0; nt < 8; nt++) {
            oc[nt][0] *= corr0; oc[nt][1] *= corr0;
            oc[nt][2] *= corr1; oc[nt][3] *= corr1;
        }

        // P -> warp-private smem (tf32-rounded)
#pragma unroll
        for (int nt = 0; nt < 8; nt++) {
            const int c = nt * 8 + 2 * tig;
            Pw[g * PSTR + c]           = __uint_as_float(f2t(s[nt][0]));
            Pw[g * PSTR + c + 1]       = __uint_as_float(f2t(s[nt][1]));
            Pw[(g + 8) * PSTR + c]     = __uint_as_float(f2t(s[nt][2]));
            Pw[(g + 8) * PSTR + c + 1] = __uint_as_float(f2t(s[nt][3]));
        }
        __syncwarp();

        // O += P @ V
#pragma unroll
        for (int kk = 0; kk < 8; kk++) {
            const unsigned a0 = __float_as_uint(Pw[g * PSTR + kk * 8 + tig]);
            const unsigned a1 = __float_as_uint(Pw[(g + 8) * PSTR + kk * 8 + tig]);
            const unsigned a2 = __float_as_uint(Pw[g * PSTR + kk * 8 + tig + 4]);
            const unsigned a3 = __float_as_uint(Pw[(g + 8) * PSTR + kk * 8 + tig + 4]);
#pragma unroll
            for (int nt = 0; nt < 8; nt++) {
                const unsigned b0 = __float_as_uint(Vs[(kk * 8 + tig) * VSTR + nt * 8 + g]);
                const unsigned b1 = __float_as_uint(Vs[(kk * 8 + 4 + tig) * VSTR + nt * 8 + g]);
                mma8(oc[nt], a0, a1, a2, a3, b0, b1);
            }
        }
        __syncthreads();
    }

    // Normalize + write
    const float inv0 = 1.0f / l0;
    const float inv1 = 1.0f / l1;
    const size_t row = (size_t)b * L_ + qblk * 64 + wid * 16 + g;
#pragma unroll
    for (int nt = 0; nt < 8; nt++) {
        const int c = h * HD_ + nt * 8 + 2 * tig;
        float2 lo = make_float2(oc[nt][0] * inv0, oc[nt][1] * inv0);
        float2 hi = make_float2(oc[nt][2] * inv1, oc[nt][3] * inv1);
        *reinterpret_cast<float2*>(out + row * D_ + c)       = lo;
        *reinterpret_cast<float2*>(out + (row + 8) * D_ + c) = hi;
    }
}

// ---------------------------------------------------------------------------
// Host launcher
// ---------------------------------------------------------------------------
extern "C" void kernel_launch(void* const* d_in, const int* in_sizes, int n_in,
                              void* d_out, int out_size)
{
    const float* x     = (const float*)d_in[0];
    const float* Wqkv  = (const float*)d_in[1];
    const float* bqkv  = (const float*)d_in[2];
    const float* Wproj = (const float*)d_in[3];
    const float* bproj = (const float*)d_in[4];
    float* out = (float*)d_out;

    float* qkv; float* att;
    cudaGetSymbolAddress((void**)&qkv, g_qkv);
    cudaGetSymbolAddress((void**)&att, g_att);

    static bool attr_set = false;
    if (!attr_set) {
        cudaFuncSetAttribute(attn_tf32,
                             cudaFuncAttributeMaxDynamicSharedMemorySize,
                             ATT_SMEM);
        attr_set = true;
    }

    // 1) QKV projection
    {
        dim3 grid(QKV_N / 128, ML_ / 128);
        gemm_tf32<<<grid, 256>>>(x, Wqkv, bqkv, qkv, ML_, QKV_N, D_);
    }
    // 2) Attention
    {
        dim3 grid(L_ / 64, H_, B_);
        attn_tf32<<<grid, 128, ATT_SMEM>>>(qkv, att);
    }
    // 3) Output projection
    {
        dim3 grid(D_ / 128, ML_ / 128);
        gemm_tf32<<<grid, 256>>>(att, Wproj, bproj, out, ML_, D_, D_);
    }
}

// round 3
// speedup vs baseline: 3.7450x; 1.0681x over previous
#include <cuda_runtime.h>
#include <math.h>

// Problem constants
#define B_   2
#define L_   2048
#define D_   768
#define H_   12
#define HD_  64
#define ML_  (B_ * L_)          // 4096
#define QKV_N (3 * D_)          // 2304
#define SCALE_ 0.125f

// Scratch (device globals — no allocation allowed)
__device__ float g_qkv[(size_t)ML_ * QKV_N];    // [4096, 2304] (tf32-rounded)
__device__ float g_att[(size_t)ML_ * D_];       // [4096, 768]  (tf32-rounded)
__device__ float g_x[(size_t)ML_ * D_];         // x, tf32-rounded
__device__ float g_wqkv[(size_t)D_ * QKV_N];    // Wqkv, tf32-rounded
__device__ float g_wproj[(size_t)D_ * D_];      // Wproj, tf32-rounded

// ---------------------------------------------------------------------------
// helpers
// ---------------------------------------------------------------------------
__device__ __forceinline__ unsigned f2t(float x) {
    unsigned u;
    asm("cvt.rna.tf32.f32 %0, %1;" : "=r"(u) : "f"(x));
    return u;
}
__device__ __forceinline__ float f2tf(float x) { return __uint_as_float(f2t(x)); }

__device__ __forceinline__ void mma8(float* c,
                                     unsigned a0, unsigned a1, unsigned a2, unsigned a3,
                                     unsigned b0, unsigned b1) {
    asm volatile(
        "mma.sync.aligned.m16n8k8.row.col.f32.tf32.tf32.f32 "
        "{%0,%1,%2,%3},{%4,%5,%6,%7},{%8,%9},{%0,%1,%2,%3};"
        : "+f"(c[0]), "+f"(c[1]), "+f"(c[2]), "+f"(c[3])
        : "r"(a0), "r"(a1), "r"(a2), "r"(a3), "r"(b0), "r"(b1));
}

__device__ __forceinline__ void cpa16(unsigned dst, const float* src) {
    asm volatile("cp.async.cg.shared.global [%0], [%1], 16;\n" :: "r"(dst), "l"(src));
}
#define CP_COMMIT() asm volatile("cp.async.commit_group;\n" ::: "memory")
#define CP_WAIT(n)  asm volatile("cp.async.wait_group %0;\n" :: "n"(n) : "memory")

// ---------------------------------------------------------------------------
// Pre-round to tf32 (rna) copy kernel, float4 grid-stride
// ---------------------------------------------------------------------------
__global__ void round_tf32_kernel(const float* __restrict__ in,
                                  float* __restrict__ out, int n4)
{
    int i = blockIdx.x * blockDim.x + threadIdx.x;
    if (i < n4) {
        float4 v = reinterpret_cast<const float4*>(in)[i];
        v.x = f2tf(v.x); v.y = f2tf(v.y); v.z = f2tf(v.z); v.w = f2tf(v.w);
        reinterpret_cast<float4*>(out)[i] = v;
    }
}

// ---------------------------------------------------------------------------
// tf32 GEMM + bias, cp.async double-buffered.
// Inputs must already be tf32-exact. C = A[M,K]@B[K,N] + bias.
// 128x128x32 tiles, 256 thr (8 warps 2x4), warp 64x32, mma m16n8k8.
// ROUND_OUT: round stored C to tf32 (rna).
// ---------------------------------------------------------------------------
#define ASTR 36
#define BSTR 136
#define GEMM_SMEM ((2 * 128 * ASTR + 2 * 32 * BSTR) * 4)

template <bool ROUND_OUT>
__global__ __launch_bounds__(256)
void gemm_tf32(const float* __restrict__ A, const float* __restrict__ Bm,
               const float* __restrict__ bias, float* __restrict__ C,
               int M, int N, int K)
{
    extern __shared__ float sm[];
    float* As = sm;                       // [2][128][ASTR]
    float* Bs = sm + 2 * 128 * ASTR;      // [2][32][BSTR]

    const int tid  = threadIdx.x;
    const int wid  = tid >> 5;
    const int lane = tid & 31;
    const int g    = lane >> 2;
    const int tig  = lane & 3;
    const int wm   = wid >> 2;
    const int wn   = wid & 3;
    const int row0 = blockIdx.y * 128;
    const int col0 = blockIdx.x * 128;

    const int aR = tid >> 3, aC = (tid & 7) * 4;
    const int bR = tid >> 5, bC = (tid & 31) * 4;

    const unsigned sA = (unsigned)__cvta_generic_to_shared(As);
    const unsigned sB = (unsigned)__cvta_generic_to_shared(Bs);

    float acc[4][4][4];
#pragma unroll
    for (int mt = 0; mt < 4; mt++)
#pragma unroll
        for (int nt = 0; nt < 4; nt++)
#pragma unroll
            for (int i = 0; i < 4; i++) acc[mt][nt][i] = 0.0f;

    const int T = K >> 5;

    // stage tile t into buffer buf
    auto stage = [&](int t, int buf) {
        const int k0 = t << 5;
#pragma unroll
        for (int i = 0; i < 4; i++) {
            const int r = aR + i * 32;
            cpa16(sA + (unsigned)((buf * 128 * ASTR + r * ASTR + aC) * 4),
                  A + (size_t)(row0 + r) * K + k0 + aC);
        }
#pragma unroll
        for (int i = 0; i < 4; i++) {
            const int r = bR + i * 8;
            cpa16(sB + (unsigned)((buf * 32 * BSTR + r * BSTR + bC) * 4),
                  Bm + (size_t)(k0 + r) * N + col0 + bC);
        }
    };

    stage(0, 0);
    CP_COMMIT();

    int buf = 0;
    for (int t = 0; t < T; t++) {
        if (t + 1 < T) {
            stage(t + 1, buf ^ 1);
            CP_COMMIT();
            CP_WAIT(1);
        } else {
            CP_WAIT(0);
        }
        __syncthreads();

        const float* Ab = As + buf * 128 * ASTR;
        const float* Bb = Bs + buf * 32 * BSTR;
#pragma unroll
        for (int kk = 0; kk < 4; kk++) {
            unsigned af[4][4], bf[4][2];
#pragma unroll
            for (int mt = 0; mt < 4; mt++) {
                const int r = wm * 64 + mt * 16 + g;
                af[mt][0] = __float_as_uint(Ab[r * ASTR + kk * 8 + tig]);
                af[mt][1] = __float_as_uint(Ab[(r + 8) * ASTR + kk * 8 + tig]);
                af[mt][2] = __float_as_uint(Ab[r * ASTR + kk * 8 + tig + 4]);
                af[mt][3] = __float_as_uint(Ab[(r + 8) * ASTR + kk * 8 + tig + 4]);
            }
#pragma unroll
            for (int nt = 0; nt < 4; nt++) {
                const int c = wn * 32 + nt * 8 + g;
                bf[nt][0] = __float_as_uint(Bb[(kk * 8 + tig) * BSTR + c]);
                bf[nt][1] = __float_as_uint(Bb[(kk * 8 + tig + 4) * BSTR + c]);
            }
#pragma unroll
            for (int mt = 0; mt < 4; mt++)
#pragma unroll
                for (int nt = 0; nt < 4; nt++)
                    mma8(acc[mt][nt], af[mt][0], af[mt][1], af[mt][2], af[mt][3],
                         bf[nt][0], bf[nt][1]);
        }
        __syncthreads();
        buf ^= 1;
    }

#pragma unroll
    for (int mt = 0; mt < 4; mt++) {
        const int r = row0 + wm * 64 + mt * 16 + g;
#pragma unroll
        for (int nt = 0; nt < 4; nt++) {
            const int c = col0 + wn * 32 + nt * 8 + tig * 2;
            const float b0v = bias[c], b1v = bias[c + 1];
            float2 lo, hi;
            if (ROUND_OUT) {
                lo = make_float2(f2tf(acc[mt][nt][0] + b0v), f2tf(acc[mt][nt][1] + b1v));
                hi = make_float2(f2tf(acc[mt][nt][2] + b0v), f2tf(acc[mt][nt][3] + b1v));
            } else {
                lo = make_float2(acc[mt][nt][0] + b0v, acc[mt][nt][1] + b1v);
                hi = make_float2(acc[mt][nt][2] + b0v, acc[mt][nt][3] + b1v);
            }
            *reinterpret_cast<float2*>(C + (size_t)r * N + c)       = lo;
            *reinterpret_cast<float2*>(C + (size_t)(r + 8) * N + c) = hi;
        }
    }
}

// ---------------------------------------------------------------------------
// Flash attention, tf32 MMA, cp.async double-buffered K/V.
// CTA = (128 q-rows, head, batch), 8 warps x 16 rows. K/V tile = 64 keys.
// g_qkv is tf32-exact; SCALE_=0.125 is a power of two (exact rescale).
// ---------------------------------------------------------------------------
#define KSTR 68
#define VSTR 72
#define PSTR 68
#define ATT_WARPS 8
#define ATT_SMEM ((2 * 64 * KSTR + 2 * 64 * VSTR + ATT_WARPS * 16 * PSTR) * 4)

__global__ __launch_bounds__(ATT_WARPS * 32)
void attn_tf32(const float* __restrict__ qkv, float* __restrict__ out)
{
    extern __shared__ float sm[];
    float* Ks = sm;                          // [2][64][KSTR]
    float* Vs = Ks + 2 * 64 * KSTR;          // [2][64][VSTR]
    float* Ps = Vs + 2 * 64 * VSTR;          // [8][16][PSTR]

    const int tid  = threadIdx.x;
    const int wid  = tid >> 5;
    const int lane = tid & 31;
    const int g    = lane >> 2;
    const int tig  = lane & 3;
    const int qblk = blockIdx.x;      // 0..15 (128 rows each)
    const int h    = blockIdx.y;
    const int b    = blockIdx.z;

    const size_t rs    = QKV_N;
    const size_t baseQ = ((size_t)b * L_ + qblk * 128) * rs + h * HD_;
    const size_t baseK = (size_t)b * L_ * rs + D_ + h * HD_;
    const size_t baseV = (size_t)b * L_ * rs + 2 * D_ + h * HD_;

    const unsigned sK = (unsigned)__cvta_generic_to_shared(Ks);
    const unsigned sV = (unsigned)__cvta_generic_to_shared(Vs);

    // Q fragments, pre-scaled (exact power-of-two), register-resident
    unsigned qa[8][4];
    {
        const float* q0 = qkv + baseQ + (size_t)(wid * 16 + g) * rs;
        const float* q8 = q0 + 8 * rs;
#pragma unroll
        for (int kk = 0; kk < 8; kk++) {
            const int c = kk * 8 + tig;
            qa[kk][0] = __float_as_uint(q0[c] * SCALE_);
            qa[kk][1] = __float_as_uint(q8[c] * SCALE_);
            qa[kk][2] = __float_as_uint(q0[c + 4] * SCALE_);
            qa[kk][3] = __float_as_uint(q8[c + 4] * SCALE_);
        }
    }

    float oc[8][4];
#pragma unroll
    for (int nt = 0; nt < 8; nt++)
#pragma unroll
        for (int i = 0; i < 4; i++) oc[nt][i] = 0.0f;
    float m0 = -INFINITY, m1 = -INFINITY, l0 = 0.0f, l1 = 0.0f;

    float* Pw = Ps + wid * 16 * PSTR;

    // stage K/V tile t into buffer buf (raw 16B copies)
    auto stage = [&](int t, int buf) {
        const int j0 = t << 6;
#pragma unroll
        for (int e = tid; e < 64 * 16; e += ATT_WARPS * 32) {
            const int r = e >> 4;
            const int c = (e & 15) * 4;
            cpa16(sK + (unsigned)((buf * 64 * KSTR + r * KSTR + c) * 4),
                  qkv + baseK + (size_t)(j0 + r) * rs + c);
            cpa16(sV + (unsigned)((buf * 64 * VSTR + r * VSTR + c) * 4),
                  qkv + baseV + (size_t)(j0 + r) * rs + c);
        }
    };

    stage(0, 0);
    CP_COMMIT();

    int buf = 0;
    const int T = L_ / 64;
    for (int t = 0; t < T; t++) {
        if (t + 1 < T) {
            stage(t + 1, buf ^ 1);
            CP_COMMIT();
            CP_WAIT(1);
        } else {
            CP_WAIT(0);
        }
        __syncthreads();

        const float* Kb = Ks + buf * 64 * KSTR;
        const float* Vb = Vs + buf * 64 * VSTR;

        // S = (Q*scale) @ K^T
        float s[8][4];
#pragma unroll
        for (int nt = 0; nt < 8; nt++)
#pragma unroll
            for (int i = 0; i < 4; i++) s[nt][i] = 0.0f;

#pragma unroll
        for (int kk = 0; kk < 8; kk++) {
#pragma unroll
            for (int nt = 0; nt < 8; nt++) {
                const unsigned b0 = __float_as_uint(Kb[(nt * 8 + g) * KSTR + kk * 8 + tig]);
                const unsigned b1 = __float_as_uint(Kb[(nt * 8 + g) * KSTR + kk * 8 + tig + 4]);
                mma8(s[nt], qa[kk][0], qa[kk][1], qa[kk][2], qa[kk][3], b0, b1);
            }
        }

        // Online softmax
        float mx0 = -INFINITY, mx1 = -INFINITY;
#pragma unroll
        for (int nt = 0; nt < 8; nt++) {
            mx0 = fmaxf(mx0, fmaxf(s[nt][0], s[nt][1]));
            mx1 = fmaxf(mx1, fmaxf(s[nt][2], s[nt][3]));
        }
        mx0 = fmaxf(mx0, __shfl_xor_sync(0xffffffffu, mx0, 1));
        mx0 = fmaxf(mx0, __shfl_xor_sync(0xffffffffu, mx0, 2));
        mx1 = fmaxf(mx1, __shfl_xor_sync(0xffffffffu, mx1, 1));
        mx1 = fmaxf(mx1, __shfl_xor_sync(0xffffffffu, mx1, 2));

        const float mn0 = fmaxf(m0, mx0);
        const float mn1 = fmaxf(m1, mx1);
        const float corr0 = __expf(m0 - mn0);
        const float corr1 = __expf(m1 - mn1);
        m0 = mn0; m1 = mn1;

        float sum0 = 0.0f, sum1 = 0.0f;
#pragma unroll
        for (int nt = 0; nt < 8; nt++) {
            s[nt][0] = __expf(s[nt][0] - mn0); sum0 += s[nt][0];
            s[nt][1] = __expf(s[nt][1] - mn0); sum0 += s[nt][1];
            s[nt][2] = __expf(s[nt][2] - mn1); sum1 += s[nt][2];
            s[nt][3] = __expf(s[nt][3] - mn1); sum1 += s[nt][3];
        }
        sum0 += __shfl_xor_sync(0xffffffffu, sum0, 1);
        sum0 += __shfl_xor_sync(0xffffffffu, sum0, 2);
        sum1 += __shfl_xor_sync(0xffffffffu, sum1, 1);
        sum1 += __shfl_xor_sync(0xffffffffu, sum1, 2);

        l0 = l0 * corr0 + sum0;
        l1 = l1 * corr1 + sum1;
#pragma unroll
        for (int nt = 0; nt < 8; nt++) {
            oc[nt][0] *= corr0; oc[nt][1] *= corr0;
            oc[nt][2] *= corr1; oc[nt][3] *= corr1;
        }

        // P -> warp-private smem (tf32-rounded)
#pragma unroll
        for (int nt = 0; nt < 8; nt++) {
            const int c = nt * 8 + 2 * tig;
            Pw[g * PSTR + c]           = f2tf(s[nt][0]);
            Pw[g * PSTR + c + 1]       = f2tf(s[nt][1]);
            Pw[(g + 8) * PSTR + c]     = f2tf(s[nt][2]);
            Pw[(g + 8) * PSTR + c + 1] = f2tf(s[nt][3]);
        }
        __syncwarp();

        // O += P @ V
#pragma unroll
        for (int kk = 0; kk < 8; kk++) {
            const unsigned a0 = __float_as_uint(Pw[g * PSTR + kk * 8 + tig]);
            const unsigned a1 = __float_as_uint(Pw[(g + 8) * PSTR + kk * 8 + tig]);
            const unsigned a2 = __float_as_uint(Pw[g * PSTR + kk * 8 + tig + 4]);
            const unsigned a3 = __float_as_uint(Pw[(g + 8) * PSTR + kk * 8 + tig + 4]);
#pragma unroll
            for (int nt = 0; nt < 8; nt++) {
                const unsigned b0 = __float_as_uint(Vb[(kk * 8 + tig) * VSTR + nt * 8 + g]);
                const unsigned b1 = __float_as_uint(Vb[(kk * 8 + 4 + tig) * VSTR + nt * 8 + g]);
                mma8(oc[nt], a0, a1, a2, a3, b0, b1);
            }
        }
        __syncthreads();
        buf ^= 1;
    }

    // Normalize + write (tf32-rounded: consumed by proj GEMM)
    const float inv0 = 1.0f / l0;
    const float inv1 = 1.0f / l1;
    const size_t row = (size_t)b * L_ + qblk * 128 + wid * 16 + g;
#pragma unroll
    for (int nt = 0; nt < 8; nt++) {
        const int c = h * HD_ + nt * 8 + 2 * tig;
        float2 lo = make_float2(f2tf(oc[nt][0] * inv0), f2tf(oc[nt][1] * inv0));
        float2 hi = make_float2(f2tf(oc[nt][2] * inv1), f2tf(oc[nt][3] * inv1));
        *reinterpret_cast<float2*>(out + row * D_ + c)       = lo;
        *reinterpret_cast<float2*>(out + (row + 8) * D_ + c) = hi;
    }
}

// ---------------------------------------------------------------------------
// Host launcher
// ---------------------------------------------------------------------------
extern "C" void kernel_launch(void* const* d_in, const int* in_sizes, int n_in,
                              void* d_out, int out_size)
{
    const float* x     = (const float*)d_in[0];
    const float* Wqkv  = (const float*)d_in[1];
    const float* bqkv  = (const float*)d_in[2];
    const float* Wproj = (const float*)d_in[3];
    const float* bproj = (const float*)d_in[4];
    float* out = (float*)d_out;

    float *qkv, *att, *xr, *wqkvr, *wprojr;
    cudaGetSymbolAddress((void**)&qkv,    g_qkv);
    cudaGetSymbolAddress((void**)&att,    g_att);
    cudaGetSymbolAddress((void**)&xr,     g_x);
    cudaGetSymbolAddress((void**)&wqkvr,  g_wqkv);
    cudaGetSymbolAddress((void**)&wprojr, g_wproj);

    static bool attr_set = false;
    if (!attr_set) {
        cudaFuncSetAttribute(attn_tf32,
                             cudaFuncAttributeMaxDynamicSharedMemorySize, ATT_SMEM);
        cudaFuncSetAttribute(gemm_tf32<true>,
                             cudaFuncAttributeMaxDynamicSharedMemorySize, GEMM_SMEM);
        cudaFuncSetAttribute(gemm_tf32<false>,
                             cudaFuncAttributeMaxDynamicSharedMemorySize, GEMM_SMEM);
        attr_set = true;
    }

    // 0) Pre-round inputs to tf32 (rna)
    {
        int n4;
        n4 = ML_ * D_ / 4;
        round_tf32_kernel<<<(n4 + 255) / 256, 256>>>(x, xr, n4);
        n4 = D_ * QKV_N / 4;
        round_tf32_kernel<<<(n4 + 255) / 256, 256>>>(Wqkv, wqkvr, n4);
        n4 = D_ * D_ / 4;
        round_tf32_kernel<<<(n4 + 255) / 256, 256>>>(Wproj, wprojr, n4);
    }

    // 1) QKV projection (output tf32-rounded)
    {
        dim3 grid(QKV_N / 128, ML_ / 128);
        gemm_tf32<true><<<grid, 256, GEMM_SMEM>>>(xr, wqkvr, bqkv, qkv, ML_, QKV_N, D_);
    }
    // 2) Attention (output tf32-rounded)
    {
        dim3 grid(L_ / 128, H_, B_);
        attn_tf32<<<grid, ATT_WARPS * 32, ATT_SMEM>>>(qkv, att);
    }
    // 3) Output projection (full fp32 output)
    {
        dim3 grid(D_ / 128, ML_ / 128);
        gemm_tf32<false><<<grid, 256, GEMM_SMEM>>>(att, wprojr, bproj, out, ML_, D_, D_);
    }
}

// round 4
// speedup vs baseline: 3.9603x; 1.0575x over previous
#include <cuda_runtime.h>
#include <math.h>

// Problem constants
#define B_   2
#define L_   2048
#define D_   768
#define H_   12
#define HD_  64
#define ML_  (B_ * L_)          // 4096
#define QKV_N (3 * D_)          // 2304
#define SCALE_ 0.125f

// Scratch (device globals — no allocation allowed)
__device__ float g_qkv[(size_t)ML_ * QKV_N];    // [4096, 2304] (tf32-rounded)
__device__ float g_att[(size_t)ML_ * D_];       // [4096, 768]  (tf32-rounded)
__device__ float g_x[(size_t)ML_ * D_];         // x, tf32-rounded
__device__ float g_wqkv[(size_t)D_ * QKV_N];    // Wqkv, tf32-rounded
__device__ float g_wproj[(size_t)D_ * D_];      // Wproj, tf32-rounded

// ---------------------------------------------------------------------------
// helpers
// ---------------------------------------------------------------------------
__device__ __forceinline__ unsigned f2t(float x) {
    unsigned u;
    asm("cvt.rna.tf32.f32 %0, %1;" : "=r"(u) : "f"(x));
    return u;
}
__device__ __forceinline__ float f2tf(float x) { return __uint_as_float(f2t(x)); }

__device__ __forceinline__ void mma8(float* c,
                                     unsigned a0, unsigned a1, unsigned a2, unsigned a3,
                                     unsigned b0, unsigned b1) {
    asm volatile(
        "mma.sync.aligned.m16n8k8.row.col.f32.tf32.tf32.f32 "
        "{%0,%1,%2,%3},{%4,%5,%6,%7},{%8,%9},{%0,%1,%2,%3};"
        : "+f"(c[0]), "+f"(c[1]), "+f"(c[2]), "+f"(c[3])
        : "r"(a0), "r"(a1), "r"(a2), "r"(a3), "r"(b0), "r"(b1));
}

__device__ __forceinline__ void cpa16(unsigned dst, const float* src) {
    asm volatile("cp.async.cg.shared.global [%0], [%1], 16;\n" :: "r"(dst), "l"(src));
}
#define CP_COMMIT() asm volatile("cp.async.commit_group;\n" ::: "memory")
#define CP_WAIT(n)  asm volatile("cp.async.wait_group %0;\n" :: "n"(n) : "memory")

// ---------------------------------------------------------------------------
// Pre-round to tf32 (rna) copy kernel
// ---------------------------------------------------------------------------
__global__ void round_tf32_kernel(const float* __restrict__ in,
                                  float* __restrict__ out, int n4)
{
    int i = blockIdx.x * blockDim.x + threadIdx.x;
    if (i < n4) {
        float4 v = reinterpret_cast<const float4*>(in)[i];
        v.x = f2tf(v.x); v.y = f2tf(v.y); v.z = f2tf(v.z); v.w = f2tf(v.w);
        reinterpret_cast<float4*>(out)[i] = v;
    }
}

// ---------------------------------------------------------------------------
// tf32 GEMM + bias, cp.async double-buffered, 2 CTAs/SM.
// Inputs must already be tf32-exact. C = A[M,K]@B[K,N] + bias.
// 128x128x32 tiles, 256 thr (8 warps 2x4), warp 64x32, mma m16n8k8.
// ---------------------------------------------------------------------------
#define ASTR 36
#define BSTR 136
#define GEMM_SMEM ((2 * 128 * ASTR + 2 * 32 * BSTR) * 4)

template <bool ROUND_OUT>
__global__ __launch_bounds__(256, 2)
void gemm_tf32(const float* __restrict__ A, const float* __restrict__ Bm,
               const float* __restrict__ bias, float* __restrict__ C,
               int M, int N, int K)
{
    extern __shared__ float sm[];
    float* As = sm;                       // [2][128][ASTR]
    float* Bs = sm + 2 * 128 * ASTR;      // [2][32][BSTR]

    const int tid  = threadIdx.x;
    const int wid  = tid >> 5;
    const int lane = tid & 31;
    const int g    = lane >> 2;
    const int tig  = lane & 3;
    const int wm   = wid >> 2;
    const int wn   = wid & 3;
    const int row0 = blockIdx.y * 128;
    const int col0 = blockIdx.x * 128;

    const int aR = tid >> 3, aC = (tid & 7) * 4;
    const int bR = tid >> 5, bC = (tid & 31) * 4;

    const unsigned sA = (unsigned)__cvta_generic_to_shared(As);
    const unsigned sB = (unsigned)__cvta_generic_to_shared(Bs);

    float acc[4][4][4];
#pragma unroll
    for (int mt = 0; mt < 4; mt++)
#pragma unroll
        for (int nt = 0; nt < 4; nt++)
#pragma unroll
            for (int i = 0; i < 4; i++) acc[mt][nt][i] = 0.0f;

    const int T = K >> 5;

    auto stage = [&](int t, int buf) {
        const int k0 = t << 5;
#pragma unroll
        for (int i = 0; i < 4; i++) {
            const int r = aR + i * 32;
            cpa16(sA + (unsigned)((buf * 128 * ASTR + r * ASTR + aC) * 4),
                  A + (size_t)(row0 + r) * K + k0 + aC);
        }
#pragma unroll
        for (int i = 0; i < 4; i++) {
            const int r = bR + i * 8;
            cpa16(sB + (unsigned)((buf * 32 * BSTR + r * BSTR + bC) * 4),
                  Bm + (size_t)(k0 + r) * N + col0 + bC);
        }
    };

    stage(0, 0);
    CP_COMMIT();

    int buf = 0;
    for (int t = 0; t < T; t++) {
        if (t + 1 < T) {
            stage(t + 1, buf ^ 1);
            CP_COMMIT();
            CP_WAIT(1);
        } else {
            CP_WAIT(0);
        }
        __syncthreads();

        const float* Ab = As + buf * 128 * ASTR;
        const float* Bb = Bs + buf * 32 * BSTR;
#pragma unroll
        for (int kk = 0; kk < 4; kk++) {
            unsigned af[4][4], bf[4][2];
#pragma unroll
            for (int mt = 0; mt < 4; mt++) {
                const int r = wm * 64 + mt * 16 + g;
                af[mt][0] = __float_as_uint(Ab[r * ASTR + kk * 8 + tig]);
                af[mt][1] = __float_as_uint(Ab[(r + 8) * ASTR + kk * 8 + tig]);
                af[mt][2] = __float_as_uint(Ab[r * ASTR + kk * 8 + tig + 4]);
                af[mt][3] = __float_as_uint(Ab[(r + 8) * ASTR + kk * 8 + tig + 4]);
            }
#pragma unroll
            for (int nt = 0; nt < 4; nt++) {
                const int c = wn * 32 + nt * 8 + g;
                bf[nt][0] = __float_as_uint(Bb[(kk * 8 + tig) * BSTR + c]);
                bf[nt][1] = __float_as_uint(Bb[(kk * 8 + tig + 4) * BSTR + c]);
            }
#pragma unroll
            for (int mt = 0; mt < 4; mt++)
#pragma unroll
                for (int nt = 0; nt < 4; nt++)
                    mma8(acc[mt][nt], af[mt][0], af[mt][1], af[mt][2], af[mt][3],
                         bf[nt][0], bf[nt][1]);
        }
        __syncthreads();
        buf ^= 1;
    }

#pragma unroll
    for (int mt = 0; mt < 4; mt++) {
        const int r = row0 + wm * 64 + mt * 16 + g;
#pragma unroll
        for (int nt = 0; nt < 4; nt++) {
            const int c = col0 + wn * 32 + nt * 8 + tig * 2;
            const float b0v = bias[c], b1v = bias[c + 1];
            float2 lo, hi;
            if (ROUND_OUT) {
                lo = make_float2(f2tf(acc[mt][nt][0] + b0v), f2tf(acc[mt][nt][1] + b1v));
                hi = make_float2(f2tf(acc[mt][nt][2] + b0v), f2tf(acc[mt][nt][3] + b1v));
            } else {
                lo = make_float2(acc[mt][nt][0] + b0v, acc[mt][nt][1] + b1v);
                hi = make_float2(acc[mt][nt][2] + b0v, acc[mt][nt][3] + b1v);
            }
            *reinterpret_cast<float2*>(C + (size_t)r * N + c)       = lo;
            *reinterpret_cast<float2*>(C + (size_t)(r + 8) * N + c) = hi;
        }
    }
}

// ---------------------------------------------------------------------------
// Flash attention, tf32 MMA. CTA = (128 q-rows, head, batch), 8 warps.
// K double-buffered (cp.async), V single-buffered: V(t+1) is issued right
// after PV(t) and its load overlaps S(t+1)+softmax. 2 CTAs/SM.
// ---------------------------------------------------------------------------
#define KSTR 68
#define VSTR 72
#define PSTR 68
#define ATT_WARPS 8
#define ATT_SMEM ((2 * 64 * KSTR + 64 * VSTR + ATT_WARPS * 16 * PSTR) * 4)

__global__ __launch_bounds__(ATT_WARPS * 32, 2)
void attn_tf32(const float* __restrict__ qkv, float* __restrict__ out)
{
    extern __shared__ float sm[];
    float* Ks = sm;                          // [2][64][KSTR]
    float* Vs = Ks + 2 * 64 * KSTR;          // [64][VSTR]
    float* Ps = Vs + 64 * VSTR;              // [8][16][PSTR]

    const int tid  = threadIdx.x;
    const int wid  = tid >> 5;
    const int lane = tid & 31;
    const int g    = lane >> 2;
    const int tig  = lane & 3;
    const int qblk = blockIdx.x;      // 0..15 (128 rows each)
    const int h    = blockIdx.y;
    const int b    = blockIdx.z;

    const size_t rs    = QKV_N;
    const size_t baseQ = ((size_t)b * L_ + qblk * 128) * rs + h * HD_;
    const size_t baseK = (size_t)b * L_ * rs + D_ + h * HD_;
    const size_t baseV = (size_t)b * L_ * rs + 2 * D_ + h * HD_;

    const unsigned sK = (unsigned)__cvta_generic_to_shared(Ks);
    const unsigned sV = (unsigned)__cvta_generic_to_shared(Vs);

    auto stageK = [&](int t, int buf) {
        const int j0 = t << 6;
#pragma unroll
        for (int e = tid; e < 64 * 16; e += ATT_WARPS * 32) {
            const int r = e >> 4;
            const int c = (e & 15) * 4;
            cpa16(sK + (unsigned)((buf * 64 * KSTR + r * KSTR + c) * 4),
                  qkv + baseK + (size_t)(j0 + r) * rs + c);
        }
    };
    auto stageV = [&](int t) {
        const int j0 = t << 6;
#pragma unroll
        for (int e = tid; e < 64 * 16; e += ATT_WARPS * 32) {
            const int r = e >> 4;
            const int c = (e & 15) * 4;
            cpa16(sV + (unsigned)((r * VSTR + c) * 4),
                  qkv + baseV + (size_t)(j0 + r) * rs + c);
        }
    };

    stageK(0, 0); CP_COMMIT();
    stageV(0);    CP_COMMIT();

    // Q fragments, pre-scaled (exact power-of-two), register-resident.
    // Loaded after the cp.asyncs are in flight.
    unsigned qa[8][4];
    {
        const float* q0 = qkv + baseQ + (size_t)(wid * 16 + g) * rs;
        const float* q8 = q0 + 8 * rs;
#pragma unroll
        for (int kk = 0; kk < 8; kk++) {
            const int c = kk * 8 + tig;
            qa[kk][0] = __float_as_uint(q0[c] * SCALE_);
            qa[kk][1] = __float_as_uint(q8[c] * SCALE_);
            qa[kk][2] = __float_as_uint(q0[c + 4] * SCALE_);
            qa[kk][3] = __float_as_uint(q8[c + 4] * SCALE_);
        }
    }

    float oc[8][4];
#pragma unroll
    for (int nt = 0; nt < 8; nt++)
#pragma unroll
        for (int i = 0; i < 4; i++) oc[nt][i] = 0.0f;
    float m0 = -INFINITY, m1 = -INFINITY, l0 = 0.0f, l1 = 0.0f;

    float* Pw = Ps + wid * 16 * PSTR;

    int buf = 0;
    const int T = L_ / 64;
    for (int t = 0; t < T; t++) {
        const bool has_next = (t + 1 < T);
        if (has_next) {
            stageK(t + 1, buf ^ 1);
            CP_COMMIT();
            CP_WAIT(1);     // K(t) and V(t) complete; K(t+1) may pend
        } else {
            CP_WAIT(0);
        }
        __syncthreads();

        const float* Kb = Ks + buf * 64 * KSTR;

        // S = (Q*scale) @ K^T
        float s[8][4];
#pragma unroll
        for (int nt = 0; nt < 8; nt++)
#pragma unroll
            for (int i = 0; i < 4; i++) s[nt][i] = 0.0f;

#pragma unroll
        for (int kk = 0; kk < 8; kk++) {
#pragma unroll
            for (int nt = 0; nt < 8; nt++) {
                const unsigned b0 = __float_as_uint(Kb[(nt * 8 + g) * KSTR + kk * 8 + tig]);
                const unsigned b1 = __float_as_uint(Kb[(nt * 8 + g) * KSTR + kk * 8 + tig + 4]);
                mma8(s[nt], qa[kk][0], qa[kk][1], qa[kk][2], qa[kk][3], b0, b1);
            }
        }

        // Online softmax
        float mx0 = -INFINITY, mx1 = -INFINITY;
#pragma unroll
        for (int nt = 0; nt < 8; nt++) {
            mx0 = fmaxf(mx0, fmaxf(s[nt][0], s[nt][1]));
            mx1 = fmaxf(mx1, fmaxf(s[nt][2], s[nt][3]));
        }
        mx0 = fmaxf(mx0, __shfl_xor_sync(0xffffffffu, mx0, 1));
        mx0 = fmaxf(mx0, __shfl_xor_sync(0xffffffffu, mx0, 2));
        mx1 = fmaxf(mx1, __shfl_xor_sync(0xffffffffu, mx1, 1));
        mx1 = fmaxf(mx1, __shfl_xor_sync(0xffffffffu, mx1, 2));

        const float mn0 = fmaxf(m0, mx0);
        const float mn1 = fmaxf(m1, mx1);
        const float corr0 = __expf(m0 - mn0);
        const float corr1 = __expf(m1 - mn1);
        m0 = mn0; m1 = mn1;

        float sum0 = 0.0f, sum1 = 0.0f;
#pragma unroll
        for (int nt = 0; nt < 8; nt++) {
            s[nt][0] = __expf(s[nt][0] - mn0); sum0 += s[nt][0];
            s[nt][1] = __expf(s[nt][1] - mn0); sum0 += s[nt][1];
            s[nt][2] = __expf(s[nt][2] - mn1); sum1 += s[nt][2];
            s[nt][3] = __expf(s[nt][3] - mn1); sum1 += s[nt][3];
        }
        sum0 += __shfl_xor_sync(0xffffffffu, sum0, 1);
        sum0 += __shfl_xor_sync(0xffffffffu, sum0, 2);
        sum1 += __shfl_xor_sync(0xffffffffu, sum1, 1);
        sum1 += __shfl_xor_sync(0xffffffffu, sum1, 2);

        l0 = l0 * corr0 + sum0;
        l1 = l1 * corr1 + sum1;
#pragma unroll
        for (int nt = 0; nt < 8; nt++) {
            oc[nt][0] *= corr0; oc[nt][1] *= corr0;
            oc[nt][2] *= corr1; oc[nt][3] *= corr1;
        }

        // P -> warp-private smem (tf32-rounded)
#pragma unroll
        for (int nt = 0; nt < 8; nt++) {
            const int c = nt * 8 + 2 * tig;
            Pw[g * PSTR + c]           = f2tf(s[nt][0]);
            Pw[g * PSTR + c + 1]       = f2tf(s[nt][1]);
            Pw[(g + 8) * PSTR + c]     = f2tf(s[nt][2]);
            Pw[(g + 8) * PSTR + c + 1] = f2tf(s[nt][3]);
        }
        __syncwarp();

        // O += P @ V
#pragma unroll
        for (int kk = 0; kk < 8; kk++) {
            const unsigned a0 = __float_as_uint(Pw[g * PSTR + kk * 8 + tig]);
            const unsigned a1 = __float_as_uint(Pw[(g + 8) * PSTR + kk * 8 + tig]);
            const unsigned a2 = __float_as_uint(Pw[g * PSTR + kk * 8 + tig + 4]);
            const unsigned a3 = __float_as_uint(Pw[(g + 8) * PSTR + kk * 8 + tig + 4]);
#pragma unroll
            for (int nt = 0; nt < 8; nt++) {
                const unsigned b0 = __float_as_uint(Vs[(kk * 8 + tig) * VSTR + nt * 8 + g]);
                const unsigned b1 = __float_as_uint(Vs[(kk * 8 + 4 + tig) * VSTR + nt * 8 + g]);
                mma8(oc[nt], a0, a1, a2, a3, b0, b1);
            }
        }
        __syncthreads();   // everyone done reading Vs before restaging

        if (has_next) {
            stageV(t + 1);
            CP_COMMIT();
        }
        buf ^= 1;
    }

    // Normalize + write (tf32-rounded: consumed by proj GEMM)
    const float inv0 = 1.0f / l0;
    const float inv1 = 1.0f / l1;
    const size_t row = (size_t)b * L_ + qblk * 128 + wid * 16 + g;
#pragma unroll
    for (int nt = 0; nt < 8; nt++) {
        const int c = h * HD_ + nt * 8 + 2 * tig;
        float2 lo = make_float2(f2tf(oc[nt][0] * inv0), f2tf(oc[nt][1] * inv0));
        float2 hi = make_float2(f2tf(oc[nt][2] * inv1), f2tf(oc[nt][3] * inv1));
        *reinterpret_cast<float2*>(out + row * D_ + c)       = lo;
        *reinterpret_cast<float2*>(out + (row + 8) * D_ + c) = hi;
    }
}

// ---------------------------------------------------------------------------
// Host launcher
// ---------------------------------------------------------------------------
extern "C" void kernel_launch(void* const* d_in, const int* in_sizes, int n_in,
                              void* d_out, int out_size)
{
    const float* x     = (const float*)d_in[0];
    const float* Wqkv  = (const float*)d_in[1];
    const float* bqkv  = (const float*)d_in[2];
    const float* Wproj = (const float*)d_in[3];
    const float* bproj = (const float*)d_in[4];
    float* out = (float*)d_out;

    float *qkv, *att, *xr, *wqkvr, *wprojr;
    cudaGetSymbolAddress((void**)&qkv,    g_qkv);
    cudaGetSymbolAddress((void**)&att,    g_att);
    cudaGetSymbolAddress((void**)&xr,     g_x);
    cudaGetSymbolAddress((void**)&wqkvr,  g_wqkv);
    cudaGetSymbolAddress((void**)&wprojr, g_wproj);

    static bool attr_set = false;
    if (!attr_set) {
        cudaFuncSetAttribute(attn_tf32,
                             cudaFuncAttributeMaxDynamicSharedMemorySize, ATT_SMEM);
        cudaFuncSetAttribute(gemm_tf32<true>,
                             cudaFuncAttributeMaxDynamicSharedMemorySize, GEMM_SMEM);
        cudaFuncSetAttribute(gemm_tf32<false>,
                             cudaFuncAttributeMaxDynamicSharedMemorySize, GEMM_SMEM);
        attr_set = true;
    }

    // 0) Pre-round inputs to tf32 (rna)
    {
        int n4;
        n4 = ML_ * D_ / 4;
        round_tf32_kernel<<<(n4 + 255) / 256, 256>>>(x, xr, n4);
        n4 = D_ * QKV_N / 4;
        round_tf32_kernel<<<(n4 + 255) / 256, 256>>>(Wqkv, wqkvr, n4);
        n4 = D_ * D_ / 4;
        round_tf32_kernel<<<(n4 + 255) / 256, 256>>>(Wproj, wprojr, n4);
    }

    // 1) QKV projection (output tf32-rounded)
    {
        dim3 grid(QKV_N / 128, ML_ / 128);
        gemm_tf32<true><<<grid, 256, GEMM_SMEM>>>(xr, wqkvr, bqkv, qkv, ML_, QKV_N, D_);
    }
    // 2) Attention (output tf32-rounded)
    {
        dim3 grid(L_ / 128, H_, B_);
        attn_tf32<<<grid, ATT_WARPS * 32, ATT_SMEM>>>(qkv, att);
    }
    // 3) Output projection (full fp32 output)
    {
        dim3 grid(D_ / 128, ML_ / 128);
        gemm_tf32<false><<<grid, 256, GEMM_SMEM>>>(att, wprojr, bproj, out, ML_, D_, D_);
    }
}

// round 5
// speedup vs baseline: 4.1612x; 1.0507x over previous
#include <cuda_runtime.h>
#include <math.h>

// Problem constants
#define B_   2
#define L_   2048
#define D_   768
#define H_   12
#define HD_  64
#define ML_  (B_ * L_)          // 4096
#define QKV_N (3 * D_)          // 2304
#define SCALE_ 0.125f

// Scratch (device globals — no allocation allowed)
__device__ float g_qkv[(size_t)ML_ * QKV_N];    // [4096, 2304] (tf32-rounded)
__device__ float g_att[(size_t)ML_ * D_];       // [4096, 768]  (tf32-rounded)
__device__ float g_x[(size_t)ML_ * D_];         // x, tf32-rounded
__device__ float g_wqkv[(size_t)D_ * QKV_N];    // Wqkv, tf32-rounded
__device__ float g_wproj[(size_t)D_ * D_];      // Wproj, tf32-rounded

// ---------------------------------------------------------------------------
// helpers
// ---------------------------------------------------------------------------
__device__ __forceinline__ unsigned f2t(float x) {
    unsigned u;
    asm("cvt.rna.tf32.f32 %0, %1;" : "=r"(u) : "f"(x));
    return u;
}
__device__ __forceinline__ float f2tf(float x) { return __uint_as_float(f2t(x)); }

__device__ __forceinline__ void mma8(float* c,
                                     unsigned a0, unsigned a1, unsigned a2, unsigned a3,
                                     unsigned b0, unsigned b1) {
    asm volatile(
        "mma.sync.aligned.m16n8k8.row.col.f32.tf32.tf32.f32 "
        "{%0,%1,%2,%3},{%4,%5,%6,%7},{%8,%9},{%0,%1,%2,%3};"
        : "+f"(c[0]), "+f"(c[1]), "+f"(c[2]), "+f"(c[3])
        : "r"(a0), "r"(a1), "r"(a2), "r"(a3), "r"(b0), "r"(b1));
}

__device__ __forceinline__ void cpa16(unsigned dst, const float* src) {
    asm volatile("cp.async.cg.shared.global [%0], [%1], 16;\n" :: "r"(dst), "l"(src));
}
#define CP_COMMIT() asm volatile("cp.async.commit_group;\n" ::: "memory")
#define CP_WAIT(n)  asm volatile("cp.async.wait_group %0;\n" :: "n"(n) : "memory")

// ---------------------------------------------------------------------------
// Pre-round to tf32 (rna) copy kernel
// ---------------------------------------------------------------------------
__global__ void round_tf32_kernel(const float* __restrict__ in,
                                  float* __restrict__ out, int n4)
{
    int i = blockIdx.x * blockDim.x + threadIdx.x;
    if (i < n4) {
        float4 v = reinterpret_cast<const float4*>(in)[i];
        v.x = f2tf(v.x); v.y = f2tf(v.y); v.z = f2tf(v.z); v.w = f2tf(v.w);
        reinterpret_cast<float4*>(out)[i] = v;
    }
}

// ---------------------------------------------------------------------------
// tf32 GEMM + bias, cp.async double-buffered, 2 CTAs/SM.
// 128x128x32 tiles, 128 thr (4 warps 2x2), warp tile 64x64, mma m16n8k8.
// Inputs must already be tf32-exact.
// ---------------------------------------------------------------------------
#define ASTR 36
#define BSTR 136
#define GEMM_SMEM ((2 * 128 * ASTR + 2 * 32 * BSTR) * 4)

template <bool ROUND_OUT>
__global__ __launch_bounds__(128, 2)
void gemm_tf32(const float* __restrict__ A, const float* __restrict__ Bm,
               const float* __restrict__ bias, float* __restrict__ C,
               int M, int N, int K)
{
    extern __shared__ float sm[];
    float* As = sm;                       // [2][128][ASTR]
    float* Bs = sm + 2 * 128 * ASTR;      // [2][32][BSTR]

    const int tid  = threadIdx.x;
    const int wid  = tid >> 5;
    const int lane = tid & 31;
    const int g    = lane >> 2;
    const int tig  = lane & 3;
    const int wm   = wid >> 1;            // 0..1 -> 64-row slab
    const int wn   = wid & 1;             // 0..1 -> 64-col slab
    const int row0 = blockIdx.y * 128;
    const int col0 = blockIdx.x * 128;

    const unsigned sA = (unsigned)__cvta_generic_to_shared(As);
    const unsigned sB = (unsigned)__cvta_generic_to_shared(Bs);

    float acc[4][8][4];
#pragma unroll
    for (int mt = 0; mt < 4; mt++)
#pragma unroll
        for (int nt = 0; nt < 8; nt++)
#pragma unroll
            for (int i = 0; i < 4; i++) acc[mt][nt][i] = 0.0f;

    const int T = K >> 5;

    auto stage = [&](int t, int buf) {
        const int k0 = t << 5;
#pragma unroll
        for (int i = 0; i < 8; i++) {
            const int e = tid + i * 128;
            const int r = e >> 3, c = (e & 7) * 4;
            cpa16(sA + (unsigned)((buf * 128 * ASTR + r * ASTR + c) * 4),
                  A + (size_t)(row0 + r) * K + k0 + c);
        }
#pragma unroll
        for (int i = 0; i < 8; i++) {
            const int e = tid + i * 128;
            const int r = e >> 5, c = (e & 31) * 4;
            cpa16(sB + (unsigned)((buf * 32 * BSTR + r * BSTR + c) * 4),
                  Bm + (size_t)(k0 + r) * N + col0 + c);
        }
    };

    stage(0, 0);
    CP_COMMIT();

    int buf = 0;
    for (int t = 0; t < T; t++) {
        if (t + 1 < T) {
            stage(t + 1, buf ^ 1);
            CP_COMMIT();
            CP_WAIT(1);
        } else {
            CP_WAIT(0);
        }
        __syncthreads();

        const float* Ab = As + buf * 128 * ASTR;
        const float* Bb = Bs + buf * 32 * BSTR;
#pragma unroll
        for (int kk = 0; kk < 4; kk++) {
            unsigned af[4][4], bf[8][2];
#pragma unroll
            for (int mt = 0; mt < 4; mt++) {
                const int r = wm * 64 + mt * 16 + g;
                af[mt][0] = __float_as_uint(Ab[r * ASTR + kk * 8 + tig]);
                af[mt][1] = __float_as_uint(Ab[(r + 8) * ASTR + kk * 8 + tig]);
                af[mt][2] = __float_as_uint(Ab[r * ASTR + kk * 8 + tig + 4]);
                af[mt][3] = __float_as_uint(Ab[(r + 8) * ASTR + kk * 8 + tig + 4]);
            }
#pragma unroll
            for (int nt = 0; nt < 8; nt++) {
                const int c = wn * 64 + nt * 8 + g;
                bf[nt][0] = __float_as_uint(Bb[(kk * 8 + tig) * BSTR + c]);
                bf[nt][1] = __float_as_uint(Bb[(kk * 8 + tig + 4) * BSTR + c]);
            }
#pragma unroll
            for (int mt = 0; mt < 4; mt++)
#pragma unroll
                for (int nt = 0; nt < 8; nt++)
                    mma8(acc[mt][nt], af[mt][0], af[mt][1], af[mt][2], af[mt][3],
                         bf[nt][0], bf[nt][1]);
        }
        __syncthreads();
        buf ^= 1;
    }

#pragma unroll
    for (int mt = 0; mt < 4; mt++) {
        const int r = row0 + wm * 64 + mt * 16 + g;
#pragma unroll
        for (int nt = 0; nt < 8; nt++) {
            const int c = col0 + wn * 64 + nt * 8 + tig * 2;
            const float b0v = bias[c], b1v = bias[c + 1];
            float2 lo, hi;
            if (ROUND_OUT) {
                lo = make_float2(f2tf(acc[mt][nt][0] + b0v), f2tf(acc[mt][nt][1] + b1v));
                hi = make_float2(f2tf(acc[mt][nt][2] + b0v), f2tf(acc[mt][nt][3] + b1v));
            } else {
                lo = make_float2(acc[mt][nt][0] + b0v, acc[mt][nt][1] + b1v);
                hi = make_float2(acc[mt][nt][2] + b0v, acc[mt][nt][3] + b1v);
            }
            *reinterpret_cast<float2*>(C + (size_t)r * N + c)       = lo;
            *reinterpret_cast<float2*>(C + (size_t)(r + 8) * N + c) = hi;
        }
    }
}

// ---------------------------------------------------------------------------
// Flash attention, tf32 MMA. CTA = (128 q-rows, head, batch), 4 warps,
// warp owns 32 q-rows (mt=2) so K/V fragment loads amortize over 2 m-tiles.
// K double-buffered (cp.async); V single-buffered, restaged after PV.
// ---------------------------------------------------------------------------
#define KSTR 68
#define VSTR 72
#define PSTR 68
#define ATT_WARPS 4
#define ATT_SMEM ((2 * 64 * KSTR + 64 * VSTR + ATT_WARPS * 32 * PSTR) * 4)

__global__ __launch_bounds__(ATT_WARPS * 32, 2)
void attn_tf32(const float* __restrict__ qkv, float* __restrict__ out)
{
    extern __shared__ float sm[];
    float* Ks = sm;                          // [2][64][KSTR]
    float* Vs = Ks + 2 * 64 * KSTR;          // [64][VSTR]
    float* Ps = Vs + 64 * VSTR;              // [4][32][PSTR]

    const int tid  = threadIdx.x;
    const int wid  = tid >> 5;
    const int lane = tid & 31;
    const int g    = lane >> 2;
    const int tig  = lane & 3;
    const int qblk = blockIdx.x;      // 0..15 (128 rows each)
    const int h    = blockIdx.y;
    const int b    = blockIdx.z;

    const size_t rs    = QKV_N;
    const size_t baseQ = ((size_t)b * L_ + qblk * 128) * rs + h * HD_;
    const size_t baseK = (size_t)b * L_ * rs + D_ + h * HD_;
    const size_t baseV = (size_t)b * L_ * rs + 2 * D_ + h * HD_;

    const unsigned sK = (unsigned)__cvta_generic_to_shared(Ks);
    const unsigned sV = (unsigned)__cvta_generic_to_shared(Vs);

    auto stageK = [&](int t, int buf) {
        const int j0 = t << 6;
#pragma unroll
        for (int i = 0; i < 8; i++) {
            const int e = tid + i * 128;
            const int r = e >> 4, c = (e & 15) * 4;
            cpa16(sK + (unsigned)((buf * 64 * KSTR + r * KSTR + c) * 4),
                  qkv + baseK + (size_t)(j0 + r) * rs + c);
        }
    };
    auto stageV = [&](int t) {
        const int j0 = t << 6;
#pragma unroll
        for (int i = 0; i < 8; i++) {
            const int e = tid + i * 128;
            const int r = e >> 4, c = (e & 15) * 4;
            cpa16(sV + (unsigned)((r * VSTR + c) * 4),
                  qkv + baseV + (size_t)(j0 + r) * rs + c);
        }
    };

    stageK(0, 0); CP_COMMIT();
    stageV(0);    CP_COMMIT();

    // Q fragments, pre-scaled (exact power-of-two), register-resident
    unsigned qa[2][8][4];
#pragma unroll
    for (int mt = 0; mt < 2; mt++) {
        const float* q0 = qkv + baseQ + (size_t)(wid * 32 + mt * 16 + g) * rs;
        const float* q8 = q0 + 8 * rs;
#pragma unroll
        for (int kk = 0; kk < 8; kk++) {
            const int c = kk * 8 + tig;
            qa[mt][kk][0] = __float_as_uint(q0[c] * SCALE_);
            qa[mt][kk][1] = __float_as_uint(q8[c] * SCALE_);
            qa[mt][kk][2] = __float_as_uint(q0[c + 4] * SCALE_);
            qa[mt][kk][3] = __float_as_uint(q8[c + 4] * SCALE_);
        }
    }

    float oc[2][8][4];
#pragma unroll
    for (int mt = 0; mt < 2; mt++)
#pragma unroll
        for (int nt = 0; nt < 8; nt++)
#pragma unroll
            for (int i = 0; i < 4; i++) oc[mt][nt][i] = 0.0f;
    float m0[2] = {-INFINITY, -INFINITY}, m1[2] = {-INFINITY, -INFINITY};
    float l0[2] = {0.0f, 0.0f}, l1[2] = {0.0f, 0.0f};

    float* Pw = Ps + wid * 32 * PSTR;

    int buf = 0;
    const int T = L_ / 64;
    for (int t = 0; t < T; t++) {
        const bool has_next = (t + 1 < T);
        if (has_next) {
            stageK(t + 1, buf ^ 1);
            CP_COMMIT();
            CP_WAIT(1);     // K(t), V(t) complete; K(t+1) may pend
        } else {
            CP_WAIT(0);
        }
        __syncthreads();

        const float* Kb = Ks + buf * 64 * KSTR;

        // S = (Q*scale) @ K^T, both m-tiles share K fragments
        float s[2][8][4];
#pragma unroll
        for (int mt = 0; mt < 2; mt++)
#pragma unroll
            for (int nt = 0; nt < 8; nt++)
#pragma unroll
                for (int i = 0; i < 4; i++) s[mt][nt][i] = 0.0f;

#pragma unroll
        for (int kk = 0; kk < 8; kk++) {
            unsigned bf[8][2];
#pragma unroll
            for (int nt = 0; nt < 8; nt++) {
                bf[nt][0] = __float_as_uint(Kb[(nt * 8 + g) * KSTR + kk * 8 + tig]);
                bf[nt][1] = __float_as_uint(Kb[(nt * 8 + g) * KSTR + kk * 8 + tig + 4]);
            }
#pragma unroll
            for (int mt = 0; mt < 2; mt++)
#pragma unroll
                for (int nt = 0; nt < 8; nt++)
                    mma8(s[mt][nt], qa[mt][kk][0], qa[mt][kk][1],
                         qa[mt][kk][2], qa[mt][kk][3], bf[nt][0], bf[nt][1]);
        }

        // Online softmax + P store, per m-tile
#pragma unroll
        for (int mt = 0; mt < 2; mt++) {
            float mx0 = -INFINITY, mx1 = -INFINITY;
#pragma unroll
            for (int nt = 0; nt < 8; nt++) {
                mx0 = fmaxf(mx0, fmaxf(s[mt][nt][0], s[mt][nt][1]));
                mx1 = fmaxf(mx1, fmaxf(s[mt][nt][2], s[mt][nt][3]));
            }
            mx0 = fmaxf(mx0, __shfl_xor_sync(0xffffffffu, mx0, 1));
            mx0 = fmaxf(mx0, __shfl_xor_sync(0xffffffffu, mx0, 2));
            mx1 = fmaxf(mx1, __shfl_xor_sync(0xffffffffu, mx1, 1));
            mx1 = fmaxf(mx1, __shfl_xor_sync(0xffffffffu, mx1, 2));

            const float mn0 = fmaxf(m0[mt], mx0);
            const float mn1 = fmaxf(m1[mt], mx1);
            const float corr0 = __expf(m0[mt] - mn0);
            const float corr1 = __expf(m1[mt] - mn1);
            m0[mt] = mn0; m1[mt] = mn1;

            float sum0 = 0.0f, sum1 = 0.0f;
#pragma unroll
            for (int nt = 0; nt < 8; nt++) {
                s[mt][nt][0] = __expf(s[mt][nt][0] - mn0); sum0 += s[mt][nt][0];
                s[mt][nt][1] = __expf(s[mt][nt][1] - mn0); sum0 += s[mt][nt][1];
                s[mt][nt][2] = __expf(s[mt][nt][2] - mn1); sum1 += s[mt][nt][2];
                s[mt][nt][3] = __expf(s[mt][nt][3] - mn1); sum1 += s[mt][nt][3];
            }
            sum0 += __shfl_xor_sync(0xffffffffu, sum0, 1);
            sum0 += __shfl_xor_sync(0xffffffffu, sum0, 2);
            sum1 += __shfl_xor_sync(0xffffffffu, sum1, 1);
            sum1 += __shfl_xor_sync(0xffffffffu, sum1, 2);

            l0[mt] = l0[mt] * corr0 + sum0;
            l1[mt] = l1[mt] * corr1 + sum1;
#pragma unroll
            for (int nt = 0; nt < 8; nt++) {
                oc[mt][nt][0] *= corr0; oc[mt][nt][1] *= corr0;
                oc[mt][nt][2] *= corr1; oc[mt][nt][3] *= corr1;
            }

            // P -> warp-private smem (tf32-rounded), float2 stores
            const int rp = mt * 16 + g;
#pragma unroll
            for (int nt = 0; nt < 8; nt++) {
                const int c = nt * 8 + 2 * tig;
                *reinterpret_cast<float2*>(&Pw[rp * PSTR + c]) =
                    make_float2(f2tf(s[mt][nt][0]), f2tf(s[mt][nt][1]));
                *reinterpret_cast<float2*>(&Pw[(rp + 8) * PSTR + c]) =
                    make_float2(f2tf(s[mt][nt][2]), f2tf(s[mt][nt][3]));
            }
        }
        __syncwarp();

        // O += P @ V, both m-tiles share V fragments
#pragma unroll
        for (int kk = 0; kk < 8; kk++) {
            unsigned pa[2][4];
#pragma unroll
            for (int mt = 0; mt < 2; mt++) {
                const int rp = mt * 16 + g;
                pa[mt][0] = __float_as_uint(Pw[rp * PSTR + kk * 8 + tig]);
                pa[mt][1] = __float_as_uint(Pw[(rp + 8) * PSTR + kk * 8 + tig]);
                pa[mt][2] = __float_as_uint(Pw[rp * PSTR + kk * 8 + tig + 4]);
                pa[mt][3] = __float_as_uint(Pw[(rp + 8) * PSTR + kk * 8 + tig + 4]);
            }
            unsigned bf[8][2];
#pragma unroll
            for (int nt = 0; nt < 8; nt++) {
                bf[nt][0] = __float_as_uint(Vs[(kk * 8 + tig) * VSTR + nt * 8 + g]);
                bf[nt][1] = __float_as_uint(Vs[(kk * 8 + 4 + tig) * VSTR + nt * 8 + g]);
            }
#pragma unroll
            for (int mt = 0; mt < 2; mt++)
#pragma unroll
                for (int nt = 0; nt < 8; nt++)
                    mma8(oc[mt][nt], pa[mt][0], pa[mt][1], pa[mt][2], pa[mt][3],
                         bf[nt][0], bf[nt][1]);
        }
        __syncthreads();   // all warps done reading Vs before restaging

        if (has_next) {
            stageV(t + 1);
            CP_COMMIT();
        }
        buf ^= 1;
    }

    // Normalize + write (tf32-rounded: consumed by proj GEMM)
#pragma unroll
    for (int mt = 0; mt < 2; mt++) {
        const float inv0 = 1.0f / l0[mt];
        const float inv1 = 1.0f / l1[mt];
        const size_t row = (size_t)b * L_ + qblk * 128 + wid * 32 + mt * 16 + g;
#pragma unroll
        for (int nt = 0; nt < 8; nt++) {
            const int c = h * HD_ + nt * 8 + 2 * tig;
            float2 lo = make_float2(f2tf(oc[mt][nt][0] * inv0), f2tf(oc[mt][nt][1] * inv0));
            float2 hi = make_float2(f2tf(oc[mt][nt][2] * inv1), f2tf(oc[mt][nt][3] * inv1));
            *reinterpret_cast<float2*>(out + row * D_ + c)       = lo;
            *reinterpret_cast<float2*>(out + (row + 8) * D_ + c) = hi;
        }
    }
}

// ---------------------------------------------------------------------------
// Host launcher
// ---------------------------------------------------------------------------
extern "C" void kernel_launch(void* const* d_in, const int* in_sizes, int n_in,
                              void* d_out, int out_size)
{
    const float* x     = (const float*)d_in[0];
    const float* Wqkv  = (const float*)d_in[1];
    const float* bqkv  = (const float*)d_in[2];
    const float* Wproj = (const float*)d_in[3];
    const float* bproj = (const float*)d_in[4];
    float* out = (float*)d_out;

    float *qkv, *att, *xr, *wqkvr, *wprojr;
    cudaGetSymbolAddress((void**)&qkv,    g_qkv);
    cudaGetSymbolAddress((void**)&att,    g_att);
    cudaGetSymbolAddress((void**)&xr,     g_x);
    cudaGetSymbolAddress((void**)&wqkvr,  g_wqkv);
    cudaGetSymbolAddress((void**)&wprojr, g_wproj);

    static bool attr_set = false;
    if (!attr_set) {
        cudaFuncSetAttribute(attn_tf32,
                             cudaFuncAttributeMaxDynamicSharedMemorySize, ATT_SMEM);
        cudaFuncSetAttribute(gemm_tf32<true>,
                             cudaFuncAttributeMaxDynamicSharedMemorySize, GEMM_SMEM);
        cudaFuncSetAttribute(gemm_tf32<false>,
                             cudaFuncAttributeMaxDynamicSharedMemorySize, GEMM_SMEM);
        attr_set = true;
    }

    // 0) Pre-round inputs to tf32 (rna)
    {
        int n4;
        n4 = ML_ * D_ / 4;
        round_tf32_kernel<<<(n4 + 255) / 256, 256>>>(x, xr, n4);
        n4 = D_ * QKV_N / 4;
        round_tf32_kernel<<<(n4 + 255) / 256, 256>>>(Wqkv, wqkvr, n4);
        n4 = D_ * D_ / 4;
        round_tf32_kernel<<<(n4 + 255) / 256, 256>>>(Wproj, wprojr, n4);
    }

    // 1) QKV projection (output tf32-rounded)
    {
        dim3 grid(QKV_N / 128, ML_ / 128);
        gemm_tf32<true><<<grid, 128, GEMM_SMEM>>>(xr, wqkvr, bqkv, qkv, ML_, QKV_N, D_);
    }
    // 2) Attention (output tf32-rounded)
    {
        dim3 grid(L_ / 128, H_, B_);
        attn_tf32<<<grid, ATT_WARPS * 32, ATT_SMEM>>>(qkv, att);
    }
    // 3) Output projection (full fp32 output)
    {
        dim3 grid(D_ / 128, ML_ / 128);
        gemm_tf32<false><<<grid, 128, GEMM_SMEM>>>(att, wprojr, bproj, out, ML_, D_, D_);
    }
}

// round 7
// speedup vs baseline: 4.2123x; 1.0123x over previous
#include <cuda_runtime.h>
#include <math.h>
#include <cstdint>

// Problem constants
#define B_   2
#define L_   2048
#define D_   768
#define H_   12
#define HD_  64
#define ML_  (B_ * L_)          // 4096
#define QKV_N (3 * D_)          // 2304
#define SCALE2_ 0.18033688011112042f   // 0.125 * log2(e)

// Scratch (device globals — no allocation allowed)
__device__ float g_qkv[(size_t)ML_ * QKV_N];    // [4096, 2304] (tf32-rounded)
__device__ float g_att[(size_t)ML_ * D_];       // [4096, 768]  (tf32-rounded)
__device__ float g_x[(size_t)ML_ * D_];         // x, tf32-rounded
__device__ float g_wqkv[(size_t)D_ * QKV_N];    // Wqkv, tf32-rounded
__device__ float g_wproj[(size_t)D_ * D_];      // Wproj, tf32-rounded

// ---------------------------------------------------------------------------
// helpers
// ---------------------------------------------------------------------------
__device__ __forceinline__ unsigned f2t(float x) {
    unsigned u;
    asm("cvt.rna.tf32.f32 %0, %1;" : "=r"(u) : "f"(x));
    return u;
}
__device__ __forceinline__ float f2tf(float x) { return __uint_as_float(f2t(x)); }

__device__ __forceinline__ float ex2(float x) {
    float y;
    asm("ex2.approx.ftz.f32 %0, %1;" : "=f"(y) : "f"(x));
    return y;
}

__device__ __forceinline__ void mma8(float* c,
                                     unsigned a0, unsigned a1, unsigned a2, unsigned a3,
                                     unsigned b0, unsigned b1) {
    asm volatile(
        "mma.sync.aligned.m16n8k8.row.col.f32.tf32.tf32.f32 "
        "{%0,%1,%2,%3},{%4,%5,%6,%7},{%8,%9},{%0,%1,%2,%3};"
        : "+f"(c[0]), "+f"(c[1]), "+f"(c[2]), "+f"(c[3])
        : "r"(a0), "r"(a1), "r"(a2), "r"(a3), "r"(b0), "r"(b1));
}

__device__ __forceinline__ void cpa16(unsigned dst, const float* src) {
    asm volatile("cp.async.cg.shared.global [%0], [%1], 16;\n" :: "r"(dst), "l"(src));
}
#define CP_COMMIT() asm volatile("cp.async.commit_group;\n" ::: "memory")
#define CP_WAIT(n)  asm volatile("cp.async.wait_group %0;\n" :: "n"(n) : "memory")

// ---------------------------------------------------------------------------
// Pre-round to tf32 (rna) copy kernel
// ---------------------------------------------------------------------------
__global__ void round_tf32_kernel(const float* __restrict__ in,
                                  float* __restrict__ out, int n4)
{
    int i = blockIdx.x * blockDim.x + threadIdx.x;
    if (i < n4) {
        float4 v = reinterpret_cast<const float4*>(in)[i];
        v.x = f2tf(v.x); v.y = f2tf(v.y); v.z = f2tf(v.z); v.w = f2tf(v.w);
        reinterpret_cast<float4*>(out)[i] = v;
    }
}

// ---------------------------------------------------------------------------
// tf32 GEMM + bias, 3-stage cp.async ring, one sync per k-iter, 2 CTAs/SM.
// 128x128x32 tiles, 128 thr (4 warps 2x2), warp tile 64x64, mma m16n8k8.
// Inputs must already be tf32-exact.
// ---------------------------------------------------------------------------
#define ASTR 36
#define BSTR 136
#define NSTAGE 3
#define GEMM_SMEM ((NSTAGE * 128 * ASTR + NSTAGE * 32 * BSTR) * 4)

template <bool ROUND_OUT>
__global__ __launch_bounds__(128, 2)
void gemm_tf32(const float* __restrict__ A, const float* __restrict__ Bm,
               const float* __restrict__ bias, float* __restrict__ C,
               int M, int N, int K)
{
    extern __shared__ float sm[];
    float* As = sm;                            // [NSTAGE][128][ASTR]
    float* Bs = sm + NSTAGE * 128 * ASTR;      // [NSTAGE][32][BSTR]

    const int tid  = threadIdx.x;
    const int wid  = tid >> 5;
    const int lane = tid & 31;
    const int g    = lane >> 2;
    const int tig  = lane & 3;
    const int wm   = wid >> 1;
    const int wn   = wid & 1;
    const int row0 = blockIdx.y * 128;
    const int col0 = blockIdx.x * 128;

    const unsigned sA = (unsigned)__cvta_generic_to_shared(As);
    const unsigned sB = (unsigned)__cvta_generic_to_shared(Bs);

    float acc[4][8][4];
#pragma unroll
    for (int mt = 0; mt < 4; mt++)
#pragma unroll
        for (int nt = 0; nt < 8; nt++)
#pragma unroll
            for (int i = 0; i < 4; i++) acc[mt][nt][i] = 0.0f;

    const int T = K >> 5;

    auto stage = [&](int t, int buf) {
        const int k0 = t << 5;
#pragma unroll
        for (int i = 0; i < 8; i++) {
            const int e = tid + i * 128;
            const int r = e >> 3, c = (e & 7) * 4;
            cpa16(sA + (unsigned)((buf * 128 * ASTR + r * ASTR + c) * 4),
                  A + (size_t)(row0 + r) * K + k0 + c);
        }
#pragma unroll
        for (int i = 0; i < 8; i++) {
            const int e = tid + i * 128;
            const int r = e >> 5, c = (e & 31) * 4;
            cpa16(sB + (unsigned)((buf * 32 * BSTR + r * BSTR + c) * 4),
                  Bm + (size_t)(k0 + r) * N + col0 + c);
        }
    };

    stage(0, 0); CP_COMMIT();
    stage(1, 1); CP_COMMIT();

    int buf = 0;
    for (int t = 0; t < T; t++) {
        if (t + 2 < T) { CP_WAIT(1); } else { CP_WAIT(0); }
        __syncthreads();

        if (t + 2 < T) {
            int nb = buf + 2; if (nb >= NSTAGE) nb -= NSTAGE;
            stage(t + 2, nb);
            CP_COMMIT();
        }

        const float* Ab = As + buf * 128 * ASTR;
        const float* Bb = Bs + buf * 32 * BSTR;
#pragma unroll
        for (int kk = 0; kk < 4; kk++) {
            unsigned af[4][4], bf[8][2];
#pragma unroll
            for (int mt = 0; mt < 4; mt++) {
                const int r = wm * 64 + mt * 16 + g;
                af[mt][0] = __float_as_uint(Ab[r * ASTR + kk * 8 + tig]);
                af[mt][1] = __float_as_uint(Ab[(r + 8) * ASTR + kk * 8 + tig]);
                af[mt][2] = __float_as_uint(Ab[r * ASTR + kk * 8 + tig + 4]);
                af[mt][3] = __float_as_uint(Ab[(r + 8) * ASTR + kk * 8 + tig + 4]);
            }
#pragma unroll
            for (int nt = 0; nt < 8; nt++) {
                const int c = wn * 64 + nt * 8 + g;
                bf[nt][0] = __float_as_uint(Bb[(kk * 8 + tig) * BSTR + c]);
                bf[nt][1] = __float_as_uint(Bb[(kk * 8 + tig + 4) * BSTR + c]);
            }
#pragma unroll
            for (int mt = 0; mt < 4; mt++)
#pragma unroll
                for (int nt = 0; nt < 8; nt++)
                    mma8(acc[mt][nt], af[mt][0], af[mt][1], af[mt][2], af[mt][3],
                         bf[nt][0], bf[nt][1]);
        }
        buf++; if (buf >= NSTAGE) buf -= NSTAGE;
    }

#pragma unroll
    for (int mt = 0; mt < 4; mt++) {
        const int r = row0 + wm * 64 + mt * 16 + g;
#pragma unroll
        for (int nt = 0; nt < 8; nt++) {
            const int c = col0 + wn * 64 + nt * 8 + tig * 2;
            const float b0v = bias[c], b1v = bias[c + 1];
            float2 lo, hi;
            if (ROUND_OUT) {
                lo = make_float2(f2tf(acc[mt][nt][0] + b0v), f2tf(acc[mt][nt][1] + b1v));
                hi = make_float2(f2tf(acc[mt][nt][2] + b0v), f2tf(acc[mt][nt][3] + b1v));
            } else {
                lo = make_float2(acc[mt][nt][0] + b0v, acc[mt][nt][1] + b1v);
                hi = make_float2(acc[mt][nt][2] + b0v, acc[mt][nt][3] + b1v);
            }
            *reinterpret_cast<float2*>(C + (size_t)r * N + c)       = lo;
            *reinterpret_cast<float2*>(C + (size_t)(r + 8) * N + c) = hi;
        }
    }
}

// ---------------------------------------------------------------------------
// Flash attention, tf32 MMA, softmax in exp2 domain.
// CTA = (128 q-rows, head, batch), 4 warps x 32 q-rows.
// K double-buffered (cp.async); V single-buffered, restaged after PV.
// ---------------------------------------------------------------------------
#define KSTR 68
#define VSTR 72
#define PSTR 68
#define ATT_WARPS 4
#define ATT_SMEM ((2 * 64 * KSTR + 64 * VSTR + ATT_WARPS * 32 * PSTR) * 4)

__global__ __launch_bounds__(ATT_WARPS * 32, 2)
void attn_tf32(const float* __restrict__ qkv, float* __restrict__ out)
{
    extern __shared__ float sm[];
    float* Ks = sm;                          // [2][64][KSTR]
    float* Vs = Ks + 2 * 64 * KSTR;          // [64][VSTR]
    float* Ps = Vs + 64 * VSTR;              // [4][32][PSTR]

    const int tid  = threadIdx.x;
    const int wid  = tid >> 5;
    const int lane = tid & 31;
    const int g    = lane >> 2;
    const int tig  = lane & 3;
    const int qblk = blockIdx.x;
    const int h    = blockIdx.y;
    const int b    = blockIdx.z;

    const size_t rs    = QKV_N;
    const size_t baseQ = ((size_t)b * L_ + qblk * 128) * rs + h * HD_;
    const size_t baseK = (size_t)b * L_ * rs + D_ + h * HD_;
    const size_t baseV = (size_t)b * L_ * rs + 2 * D_ + h * HD_;

    const unsigned sK = (unsigned)__cvta_generic_to_shared(Ks);
    const unsigned sV = (unsigned)__cvta_generic_to_shared(Vs);

    auto stageK = [&](int t, int buf) {
        const int j0 = t << 6;
#pragma unroll
        for (int i = 0; i < 8; i++) {
            const int e = tid + i * 128;
            const int r = e >> 4, c = (e & 15) * 4;
            cpa16(sK + (unsigned)((buf * 64 * KSTR + r * KSTR + c) * 4),
                  qkv + baseK + (size_t)(j0 + r) * rs + c);
        }
    };
    auto stageV = [&](int t) {
        const int j0 = t << 6;
#pragma unroll
        for (int i = 0; i < 8; i++) {
            const int e = tid + i * 128;
            const int r = e >> 4, c = (e & 15) * 4;
            cpa16(sV + (unsigned)((r * VSTR + c) * 4),
                  qkv + baseV + (size_t)(j0 + r) * rs + c);
        }
    };

    stageK(0, 0); CP_COMMIT();
    stageV(0);    CP_COMMIT();

    // Q fragments scaled by 0.125*log2(e), re-rounded to tf32 (rna)
    unsigned qa[2][8][4];
#pragma unroll
    for (int mt = 0; mt < 2; mt++) {
        const float* q0 = qkv + baseQ + (size_t)(wid * 32 + mt * 16 + g) * rs;
        const float* q8 = q0 + 8 * rs;
#pragma unroll
        for (int kk = 0; kk < 8; kk++) {
            const int c = kk * 8 + tig;
            qa[mt][kk][0] = f2t(q0[c] * SCALE2_);
            qa[mt][kk][1] = f2t(q8[c] * SCALE2_);
            qa[mt][kk][2] = f2t(q0[c + 4] * SCALE2_);
            qa[mt][kk][3] = f2t(q8[c + 4] * SCALE2_);
        }
    }

    float oc[2][8][4];
#pragma unroll
    for (int mt = 0; mt < 2; mt++)
#pragma unroll
        for (int nt = 0; nt < 8; nt++)
#pragma unroll
            for (int i = 0; i < 4; i++) oc[mt][nt][i] = 0.0f;
    float m0[2] = {-INFINITY, -INFINITY}, m1[2] = {-INFINITY, -INFINITY};
    float l0[2] = {0.0f, 0.0f}, l1[2] = {0.0f, 0.0f};

    float* Pw = Ps + wid * 32 * PSTR;

    int buf = 0;
    const int T = L_ / 64;
    for (int t = 0; t < T; t++) {
        const bool has_next = (t + 1 < T);
        if (has_next) {
            stageK(t + 1, buf ^ 1);
            CP_COMMIT();
            CP_WAIT(1);
        } else {
            CP_WAIT(0);
        }
        __syncthreads();

        const float* Kb = Ks + buf * 64 * KSTR;

        // S2 = (Q*scale*log2e) @ K^T  (log2-domain scores)
        float s[2][8][4];
#pragma unroll
        for (int mt = 0; mt < 2; mt++)
#pragma unroll
            for (int nt = 0; nt < 8; nt++)
#pragma unroll
                for (int i = 0; i < 4; i++) s[mt][nt][i] = 0.0f;

#pragma unroll
        for (int kk = 0; kk < 8; kk++) {
            unsigned bf[8][2];
#pragma unroll
            for (int nt = 0; nt < 8; nt++) {
                bf[nt][0] = __float_as_uint(Kb[(nt * 8 + g) * KSTR + kk * 8 + tig]);
                bf[nt][1] = __float_as_uint(Kb[(nt * 8 + g) * KSTR + kk * 8 + tig + 4]);
            }
#pragma unroll
            for (int mt = 0; mt < 2; mt++)
#pragma unroll
                for (int nt = 0; nt < 8; nt++)
                    mma8(s[mt][nt], qa[mt][kk][0], qa[mt][kk][1],
                         qa[mt][kk][2], qa[mt][kk][3], bf[nt][0], bf[nt][1]);
        }

        // Online softmax (exp2 domain) + P store, per m-tile
#pragma unroll
        for (int mt = 0; mt < 2; mt++) {
            float mx0 = -INFINITY, mx1 = -INFINITY;
#pragma unroll
            for (int nt = 0; nt < 8; nt++) {
                mx0 = fmaxf(mx0, fmaxf(s[mt][nt][0], s[mt][nt][1]));
                mx1 = fmaxf(mx1, fmaxf(s[mt][nt][2], s[mt][nt][3]));
            }
            mx0 = fmaxf(mx0, __shfl_xor_sync(0xffffffffu, mx0, 1));
            mx0 = fmaxf(mx0, __shfl_xor_sync(0xffffffffu, mx0, 2));
            mx1 = fmaxf(mx1, __shfl_xor_sync(0xffffffffu, mx1, 1));
            mx1 = fmaxf(mx1, __shfl_xor_sync(0xffffffffu, mx1, 2));

            const float mn0 = fmaxf(m0[mt], mx0);
            const float mn1 = fmaxf(m1[mt], mx1);
            const bool keep = (mn0 == m0[mt]) && (mn1 == m1[mt]);
            const float corr0 = ex2(m0[mt] - mn0);
            const float corr1 = ex2(m1[mt] - mn1);
            m0[mt] = mn0; m1[mt] = mn1;

            float sum0 = 0.0f, sum1 = 0.0f;
#pragma unroll
            for (int nt = 0; nt < 8; nt++) {
                s[mt][nt][0] = ex2(s[mt][nt][0] - mn0); sum0 += s[mt][nt][0];
                s[mt][nt][1] = ex2(s[mt][nt][1] - mn0); sum0 += s[mt][nt][1];
                s[mt][nt][2] = ex2(s[mt][nt][2] - mn1); sum1 += s[mt][nt][2];
                s[mt][nt][3] = ex2(s[mt][nt][3] - mn1); sum1 += s[mt][nt][3];
            }
            sum0 += __shfl_xor_sync(0xffffffffu, sum0, 1);
            sum0 += __shfl_xor_sync(0xffffffffu, sum0, 2);
            sum1 += __shfl_xor_sync(0xffffffffu, sum1, 1);
            sum1 += __shfl_xor_sync(0xffffffffu, sum1, 2);

            l0[mt] = l0[mt] * corr0 + sum0;
            l1[mt] = l1[mt] * corr1 + sum1;

            // Rescale O only if some row's max moved (corr==1 is exact identity)
            if (!__all_sync(0xffffffffu, keep)) {
#pragma unroll
                for (int nt = 0; nt < 8; nt++) {
                    oc[mt][nt][0] *= corr0; oc[mt][nt][1] *= corr0;
                    oc[mt][nt][2] *= corr1; oc[mt][nt][3] *= corr1;
                }
            }

            const int rp = mt * 16 + g;
#pragma unroll
            for (int nt = 0; nt < 8; nt++) {
                const int c = nt * 8 + 2 * tig;
                *reinterpret_cast<float2*>(&Pw[rp * PSTR + c]) =
                    make_float2(f2tf(s[mt][nt][0]), f2tf(s[mt][nt][1]));
                *reinterpret_cast<float2*>(&Pw[(rp + 8) * PSTR + c]) =
                    make_float2(f2tf(s[mt][nt][2]), f2tf(s[mt][nt][3]));
            }
        }
        __syncwarp();

        // O += P @ V
#pragma unroll
        for (int kk = 0; kk < 8; kk++) {
            unsigned pa[2][4];
#pragma unroll
            for (int mt = 0; mt < 2; mt++) {
                const int rp = mt * 16 + g;
                pa[mt][0] = __float_as_uint(Pw[rp * PSTR + kk * 8 + tig]);
                pa[mt][1] = __float_as_uint(Pw[(rp + 8) * PSTR + kk * 8 + tig]);
                pa[mt][2] = __float_as_uint(Pw[rp * PSTR + kk * 8 + tig + 4]);
                pa[mt][3] = __float_as_uint(Pw[(rp + 8) * PSTR + kk * 8 + tig + 4]);
            }
            unsigned bf[8][2];
#pragma unroll
            for (int nt = 0; nt < 8; nt++) {
                bf[nt][0] = __float_as_uint(Vs[(kk * 8 + tig) * VSTR + nt * 8 + g]);
                bf[nt][1] = __float_as_uint(Vs[(kk * 8 + 4 + tig) * VSTR + nt * 8 + g]);
            }
#pragma unroll
            for (int mt = 0; mt < 2; mt++)
#pragma unroll
                for (int nt = 0; nt < 8; nt++)
                    mma8(oc[mt][nt], pa[mt][0], pa[mt][1], pa[mt][2], pa[mt][3],
                         bf[nt][0], bf[nt][1]);
        }
        __syncthreads();   // all warps done reading Vs before restaging

        if (has_next) {
            stageV(t + 1);
            CP_COMMIT();
        }
        buf ^= 1;
    }

    // Normalize + write (tf32-rounded: consumed by proj GEMM)
#pragma unroll
    for (int mt = 0; mt < 2; mt++) {
        const float inv0 = 1.0f / l0[mt];
        const float inv1 = 1.0f / l1[mt];
        const size_t row = (size_t)b * L_ + qblk * 128 + wid * 32 + mt * 16 + g;
#pragma unroll
        for (int nt = 0; nt < 8; nt++) {
            const int c = h * HD_ + nt * 8 + 2 * tig;
            float2 lo = make_float2(f2tf(oc[mt][nt][0] * inv0), f2tf(oc[mt][nt][1] * inv0));
            float2 hi = make_float2(f2tf(oc[mt][nt][2] * inv1), f2tf(oc[mt][nt][3] * inv1));
            *reinterpret_cast<float2*>(out + row * D_ + c)       = lo;
            *reinterpret_cast<float2*>(out + (row + 8) * D_ + c) = hi;
        }
    }
}

// ---------------------------------------------------------------------------
// Host launcher
// ---------------------------------------------------------------------------
extern "C" void kernel_launch(void* const* d_in, const int* in_sizes, int n_in,
                              void* d_out, int out_size)
{
    const float* x     = (const float*)d_in[0];
    const float* Wqkv  = (const float*)d_in[1];
    const float* bqkv  = (const float*)d_in[2];
    const float* Wproj = (const float*)d_in[3];
    const float* bproj = (const float*)d_in[4];
    float* out = (float*)d_out;

    float *qkv, *att, *xr, *wqkvr, *wprojr;
    cudaGetSymbolAddress((void**)&qkv,    g_qkv);
    cudaGetSymbolAddress((void**)&att,    g_att);
    cudaGetSymbolAddress((void**)&xr,     g_x);
    cudaGetSymbolAddress((void**)&wqkvr,  g_wqkv);
    cudaGetSymbolAddress((void**)&wprojr, g_wproj);

    static bool attr_set = false;
    if (!attr_set) {
        cudaFuncSetAttribute(attn_tf32,
                             cudaFuncAttributeMaxDynamicSharedMemorySize, ATT_SMEM);
        cudaFuncSetAttribute(gemm_tf32<true>,
                             cudaFuncAttributeMaxDynamicSharedMemorySize, GEMM_SMEM);
        cudaFuncSetAttribute(gemm_tf32<false>,
                             cudaFuncAttributeMaxDynamicSharedMemorySize, GEMM_SMEM);
        attr_set = true;
    }

    // 0) Pre-round inputs to tf32 (rna)
    {
        int n4;
        n4 = ML_ * D_ / 4;
        round_tf32_kernel<<<(n4 + 255) / 256, 256>>>(x, xr, n4);
        n4 = D_ * QKV_N / 4;
        round_tf32_kernel<<<(n4 + 255) / 256, 256>>>(Wqkv, wqkvr, n4);
        n4 = D_ * D_ / 4;
        round_tf32_kernel<<<(n4 + 255) / 256, 256>>>(Wproj, wprojr, n4);
    }

    // 1) QKV projection (output tf32-rounded)
    {
        dim3 grid(QKV_N / 128, ML_ / 128);
        gemm_tf32<true><<<grid, 128, GEMM_SMEM>>>(xr, wqkvr, bqkv, qkv, ML_, QKV_N, D_);
    }
    // 2) Attention (output tf32-rounded)
    {
        dim3 grid(L_ / 128, H_, B_);
        attn_tf32<<<grid, ATT_WARPS * 32, ATT_SMEM>>>(qkv, att);
    }
    // 3) Output projection (full fp32 output)
    {
        dim3 grid(D_ / 128, ML_ / 128);
        gemm_tf32<false><<<grid, 128, GEMM_SMEM>>>(att, wprojr, bproj, out, ML_, D_, D_);
    }
}

// round 8
// speedup vs baseline: 6.8247x; 1.6202x over previous
#include <cuda_runtime.h>
#include <cuda_fp16.h>
#include <math.h>
#include <cstdint>

// Problem constants
#define B_   2
#define L_   2048
#define D_   768
#define H_   12
#define HD_  64
#define ML_  (B_ * L_)          // 4096
#define QKV_N (3 * D_)          // 2304
#define SCALE2_ 0.18033688011112042f   // 0.125 * log2(e)

// Scratch (device globals — no allocation allowed)
__device__ __half g_qkvh[(size_t)ML_ * QKV_N];   // QKV output, half
__device__ __half g_atth[(size_t)ML_ * D_];      // attention output, half
__device__ __half g_xh[(size_t)ML_ * D_];        // x, half
__device__ __half g_wqkvt[(size_t)QKV_N * D_];   // Wqkv^T [2304][768], half
__device__ __half g_wprojt[(size_t)D_ * D_];     // Wproj^T [768][768], half

// ---------------------------------------------------------------------------
// helpers
// ---------------------------------------------------------------------------
__device__ __forceinline__ float ex2(float x) {
    float y;
    asm("ex2.approx.ftz.f32 %0, %1;" : "=f"(y) : "f"(x));
    return y;
}

// m16n8k16 fp16 MMA, fp32 accumulate
__device__ __forceinline__ void mma16(float* c,
                                      unsigned a0, unsigned a1, unsigned a2, unsigned a3,
                                      unsigned b0, unsigned b1) {
    asm volatile(
        "mma.sync.aligned.m16n8k16.row.col.f32.f16.f16.f32 "
        "{%0,%1,%2,%3},{%4,%5,%6,%7},{%8,%9},{%0,%1,%2,%3};"
        : "+f"(c[0]), "+f"(c[1]), "+f"(c[2]), "+f"(c[3])
        : "r"(a0), "r"(a1), "r"(a2), "r"(a3), "r"(b0), "r"(b1));
}

__device__ __forceinline__ void cpa16(unsigned dst, const void* src) {
    asm volatile("cp.async.cg.shared.global [%0], [%1], 16;\n" :: "r"(dst), "l"(src));
}
#define CP_COMMIT() asm volatile("cp.async.commit_group;\n" ::: "memory")
#define CP_WAIT(n)  asm volatile("cp.async.wait_group %0;\n" :: "n"(n) : "memory")

__device__ __forceinline__ void ldmx4t(unsigned& r0, unsigned& r1,
                                       unsigned& r2, unsigned& r3, unsigned addr) {
    asm volatile("ldmatrix.sync.aligned.m8n8.x4.trans.shared.b16 {%0,%1,%2,%3}, [%4];"
                 : "=r"(r0), "=r"(r1), "=r"(r2), "=r"(r3) : "r"(addr));
}

__device__ __forceinline__ unsigned pack_h2(float a, float b) {
    __half2 h = __floats2half2_rn(a, b);
    return *reinterpret_cast<unsigned*>(&h);
}

// ---------------------------------------------------------------------------
// Conversion prologue kernels
// ---------------------------------------------------------------------------
__global__ void roundh_kernel(const float* __restrict__ in,
                              __half* __restrict__ out, int n4)
{
    int i = blockIdx.x * blockDim.x + threadIdx.x;
    if (i < n4) {
        float4 v = reinterpret_cast<const float4*>(in)[i];
        __half2 lo = __floats2half2_rn(v.x, v.y);
        __half2 hi = __floats2half2_rn(v.z, v.w);
        *reinterpret_cast<__half2*>(out + (size_t)i * 4)     = lo;
        *reinterpret_cast<__half2*>(out + (size_t)i * 4 + 2) = hi;
    }
}

// in[R][C] float -> out[C][R] half
__global__ void transpose_roundh_kernel(const float* __restrict__ in,
                                        __half* __restrict__ out, int R, int C)
{
    __shared__ float tile[32][33];
    const int c = blockIdx.x * 32 + threadIdx.x;
    const int r = blockIdx.y * 32 + threadIdx.y;
#pragma unroll
    for (int i = 0; i < 32; i += 8)
        tile[threadIdx.y + i][threadIdx.x] = in[(size_t)(r + i) * C + c];
    __syncthreads();
    const int oc = blockIdx.y * 32 + threadIdx.x;
    const int orow = blockIdx.x * 32 + threadIdx.y;
#pragma unroll
    for (int i = 0; i < 32; i += 8)
        out[(size_t)(orow + i) * R + oc] = __float2half_rn(tile[threadIdx.x][threadIdx.y + i]);
}

// ---------------------------------------------------------------------------
// fp16 GEMM + bias: C[M,N] = A[M,K] @ Bt[N,K]^T + bias
// 128x128x32 tiles, 128 thr (4 warps 2x2), warp 64x64, mma m16n8k16.
// 2-stage cp.async double buffer, 2 CTAs/SM.
// ---------------------------------------------------------------------------
#define AS_ 40    // A smem stride (halves)
#define BS_ 40    // B smem stride (halves)
#define GEMM_SMEM ((2 * 128 * AS_ + 2 * 128 * BS_) * 2)

template <bool HALF_OUT>
__global__ __launch_bounds__(128, 2)
void gemm_h(const __half* __restrict__ A, const __half* __restrict__ Bt,
            const float* __restrict__ bias, void* __restrict__ Cv,
            int M, int N, int K)
{
    extern __shared__ __half smh[];
    __half* As = smh;                      // [2][128][AS_]
    __half* Bs = smh + 2 * 128 * AS_;      // [2][128][BS_]

    const int tid  = threadIdx.x;
    const int wid  = tid >> 5;
    const int lane = tid & 31;
    const int g    = lane >> 2;
    const int tig  = lane & 3;
    const int wm   = wid >> 1;
    const int wn   = wid & 1;
    const int row0 = blockIdx.y * 128;
    const int col0 = blockIdx.x * 128;

    const unsigned sA = (unsigned)__cvta_generic_to_shared(As);
    const unsigned sB = (unsigned)__cvta_generic_to_shared(Bs);

    float acc[4][8][4];
#pragma unroll
    for (int mt = 0; mt < 4; mt++)
#pragma unroll
        for (int nt = 0; nt < 8; nt++)
#pragma unroll
            for (int i = 0; i < 4; i++) acc[mt][nt][i] = 0.0f;

    const int T = K >> 5;   // 32 halves per stage

    auto stage = [&](int t, int buf) {
        const int k0 = t << 5;
#pragma unroll
        for (int i = 0; i < 4; i++) {       // A: 512 chunks / 128 thr
            const int e = tid + i * 128;
            const int r = e >> 2, cc = (e & 3) * 8;
            cpa16(sA + (unsigned)((buf * 128 * AS_ + r * AS_ + cc) * 2),
                  A + (size_t)(row0 + r) * K + k0 + cc);
        }
#pragma unroll
        for (int i = 0; i < 4; i++) {       // B: 512 chunks
            const int e = tid + i * 128;
            const int r = e >> 2, cc = (e & 3) * 8;
            cpa16(sB + (unsigned)((buf * 128 * BS_ + r * BS_ + cc) * 2),
                  Bt + (size_t)(col0 + r) * K + k0 + cc);
        }
    };

    stage(0, 0);
    CP_COMMIT();

    int buf = 0;
    for (int t = 0; t < T; t++) {
        if (t + 1 < T) {
            stage(t + 1, buf ^ 1);
            CP_COMMIT();
            CP_WAIT(1);
        } else {
            CP_WAIT(0);
        }
        __syncthreads();

        const __half* Ab = As + buf * 128 * AS_;
        const __half* Bb = Bs + buf * 128 * BS_;
#pragma unroll
        for (int kk = 0; kk < 2; kk++) {    // two k16 steps
            unsigned af[4][4], bf[8][2];
#pragma unroll
            for (int mt = 0; mt < 4; mt++) {
                const int r = wm * 64 + mt * 16 + g;
                const int c = kk * 16 + 2 * tig;
                af[mt][0] = *reinterpret_cast<const unsigned*>(&Ab[r * AS_ + c]);
                af[mt][1] = *reinterpret_cast<const unsigned*>(&Ab[(r + 8) * AS_ + c]);
                af[mt][2] = *reinterpret_cast<const unsigned*>(&Ab[r * AS_ + c + 8]);
                af[mt][3] = *reinterpret_cast<const unsigned*>(&Ab[(r + 8) * AS_ + c + 8]);
            }
#pragma unroll
            for (int nt = 0; nt < 8; nt++) {
                const int n = wn * 64 + nt * 8 + g;
                const int c = kk * 16 + 2 * tig;
                bf[nt][0] = *reinterpret_cast<const unsigned*>(&Bb[n * BS_ + c]);
                bf[nt][1] = *reinterpret_cast<const unsigned*>(&Bb[n * BS_ + c + 8]);
            }
#pragma unroll
            for (int mt = 0; mt < 4; mt++)
#pragma unroll
                for (int nt = 0; nt < 8; nt++)
                    mma16(acc[mt][nt], af[mt][0], af[mt][1], af[mt][2], af[mt][3],
                          bf[nt][0], bf[nt][1]);
        }
        __syncthreads();
        buf ^= 1;
    }

    // Epilogue: bias + store
#pragma unroll
    for (int mt = 0; mt < 4; mt++) {
        const int r = row0 + wm * 64 + mt * 16 + g;
#pragma unroll
        for (int nt = 0; nt < 8; nt++) {
            const int c = col0 + wn * 64 + nt * 8 + tig * 2;
            const float b0v = bias[c], b1v = bias[c + 1];
            if (HALF_OUT) {
                __half* C = (__half*)Cv;
                *reinterpret_cast<__half2*>(C + (size_t)r * N + c) =
                    __floats2half2_rn(acc[mt][nt][0] + b0v, acc[mt][nt][1] + b1v);
                *reinterpret_cast<__half2*>(C + (size_t)(r + 8) * N + c) =
                    __floats2half2_rn(acc[mt][nt][2] + b0v, acc[mt][nt][3] + b1v);
            } else {
                float* C = (float*)Cv;
                *reinterpret_cast<float2*>(C + (size_t)r * N + c) =
                    make_float2(acc[mt][nt][0] + b0v, acc[mt][nt][1] + b1v);
                *reinterpret_cast<float2*>(C + (size_t)(r + 8) * N + c) =
                    make_float2(acc[mt][nt][2] + b0v, acc[mt][nt][3] + b1v);
            }
        }
    }
}

// ---------------------------------------------------------------------------
// Flash attention, fp16 MMA, exp2 softmax. CTA = (128 q-rows, head, batch),
// 4 warps x 32 q-rows. K double-buffered cp.async; V single-buffered,
// consumed via ldmatrix.x4.trans. P staged as half.
// ---------------------------------------------------------------------------
#define KSH 72    // K smem stride (halves)
#define VSH 72
#define PSH 72
#define ATT_WARPS 4
#define ATT_SMEM ((2 * 64 * KSH + 64 * VSH + ATT_WARPS * 32 * PSH) * 2)

__global__ __launch_bounds__(ATT_WARPS * 32, 2)
void attn_h(const __half* __restrict__ qkv, __half* __restrict__ out)
{
    extern __shared__ __half smh[];
    __half* Ks = smh;                       // [2][64][KSH]
    __half* Vs = Ks + 2 * 64 * KSH;         // [64][VSH]
    __half* Ps = Vs + 64 * VSH;             // [4][32][PSH]

    const int tid  = threadIdx.x;
    const int wid  = tid >> 5;
    const int lane = tid & 31;
    const int g    = lane >> 2;
    const int tig  = lane & 3;
    const int qblk = blockIdx.x;
    const int h    = blockIdx.y;
    const int b    = blockIdx.z;

    const size_t rs    = QKV_N;
    const size_t baseQ = ((size_t)b * L_ + qblk * 128) * rs + h * HD_;
    const size_t baseK = (size_t)b * L_ * rs + D_ + h * HD_;
    const size_t baseV = (size_t)b * L_ * rs + 2 * D_ + h * HD_;

    const unsigned sK = (unsigned)__cvta_generic_to_shared(Ks);
    const unsigned sV = (unsigned)__cvta_generic_to_shared(Vs);

    auto stageK = [&](int t, int buf) {
        const int j0 = t << 6;
#pragma unroll
        for (int i = 0; i < 4; i++) {       // 512 chunks / 128 thr
            const int e = tid + i * 128;
            const int r = e >> 3, cc = (e & 7) * 8;
            cpa16(sK + (unsigned)((buf * 64 * KSH + r * KSH + cc) * 2),
                  qkv + baseK + (size_t)(j0 + r) * rs + cc);
        }
    };
    auto stageV = [&](int t) {
        const int j0 = t << 6;
#pragma unroll
        for (int i = 0; i < 4; i++) {
            const int e = tid + i * 128;
            const int r = e >> 3, cc = (e & 7) * 8;
            cpa16(sV + (unsigned)((r * VSH + cc) * 2),
                  qkv + baseV + (size_t)(j0 + r) * rs + cc);
        }
    };

    stageK(0, 0); CP_COMMIT();
    stageV(0);    CP_COMMIT();

    // Q fragments: scaled by 0.125*log2e, rounded to half, register-resident.
    // qa[mt][kk][0..3] for k16 steps kk=0..3 over HD=64.
    unsigned qa[2][4][4];
#pragma unroll
    for (int mt = 0; mt < 2; mt++) {
        const __half* q0 = qkv + baseQ + (size_t)(wid * 32 + mt * 16 + g) * rs;
        const __half* q8 = q0 + 8 * rs;
#pragma unroll
        for (int kk = 0; kk < 4; kk++) {
            const int c = kk * 16 + 2 * tig;
#pragma unroll
            for (int p = 0; p < 2; p++) {   // p=0: k, p=1: k+8
                float2 f0 = __half22float2(*reinterpret_cast<const __half2*>(q0 + c + p * 8));
                float2 f8 = __half22float2(*reinterpret_cast<const __half2*>(q8 + c + p * 8));
                qa[mt][kk][p * 2 + 0] = pack_h2(f0.x * SCALE2_, f0.y * SCALE2_);
                qa[mt][kk][p * 2 + 1] = pack_h2(f8.x * SCALE2_, f8.y * SCALE2_);
            }
        }
    }

    float oc[2][8][4];
#pragma unroll
    for (int mt = 0; mt < 2; mt++)
#pragma unroll
        for (int nt = 0; nt < 8; nt++)
#pragma unroll
            for (int i = 0; i < 4; i++) oc[mt][nt][i] = 0.0f;
    float m0[2] = {-INFINITY, -INFINITY}, m1[2] = {-INFINITY, -INFINITY};
    float l0[2] = {0.0f, 0.0f}, l1[2] = {0.0f, 0.0f};

    __half* Pw = Ps + wid * 32 * PSH;

    // ldmatrix V address pieces (per lane)
    const int vrow = (lane & 7) + ((lane >> 3) & 1) * 8;   // token within 16
    const int vcol = (lane >> 4) * 8;                      // 0 or 8

    int buf = 0;
    const int T = L_ / 64;
    for (int t = 0; t < T; t++) {
        const bool has_next = (t + 1 < T);
        if (has_next) {
            stageK(t + 1, buf ^ 1);
            CP_COMMIT();
            CP_WAIT(1);
        } else {
            CP_WAIT(0);
        }
        __syncthreads();

        const __half* Kb = Ks + buf * 64 * KSH;

        // S2 = (Q*scale*log2e) @ K^T  — 4 k16 steps over HD=64
        float s[2][8][4];
#pragma unroll
        for (int mt = 0; mt < 2; mt++)
#pragma unroll
            for (int nt = 0; nt < 8; nt++)
#pragma unroll
                for (int i = 0; i < 4; i++) s[mt][nt][i] = 0.0f;

#pragma unroll
        for (int kk = 0; kk < 4; kk++) {
            unsigned bf[8][2];
#pragma unroll
            for (int nt = 0; nt < 8; nt++) {
                const int n = nt * 8 + g;
                const int c = kk * 16 + 2 * tig;
                bf[nt][0] = *reinterpret_cast<const unsigned*>(&Kb[n * KSH + c]);
                bf[nt][1] = *reinterpret_cast<const unsigned*>(&Kb[n * KSH + c + 8]);
            }
#pragma unroll
            for (int mt = 0; mt < 2; mt++)
#pragma unroll
                for (int nt = 0; nt < 8; nt++)
                    mma16(s[mt][nt], qa[mt][kk][0], qa[mt][kk][1],
                          qa[mt][kk][2], qa[mt][kk][3], bf[nt][0], bf[nt][1]);
        }

        // Online softmax (exp2 domain) + P store (half)
#pragma unroll
        for (int mt = 0; mt < 2; mt++) {
            float mx0 = -INFINITY, mx1 = -INFINITY;
#pragma unroll
            for (int nt = 0; nt < 8; nt++) {
                mx0 = fmaxf(mx0, fmaxf(s[mt][nt][0], s[mt][nt][1]));
                mx1 = fmaxf(mx1, fmaxf(s[mt][nt][2], s[mt][nt][3]));
            }
            mx0 = fmaxf(mx0, __shfl_xor_sync(0xffffffffu, mx0, 1));
            mx0 = fmaxf(mx0, __shfl_xor_sync(0xffffffffu, mx0, 2));
            mx1 = fmaxf(mx1, __shfl_xor_sync(0xffffffffu, mx1, 1));
            mx1 = fmaxf(mx1, __shfl_xor_sync(0xffffffffu, mx1, 2));

            const float mn0 = fmaxf(m0[mt], mx0);
            const float mn1 = fmaxf(m1[mt], mx1);
            const bool keep = (mn0 == m0[mt]) && (mn1 == m1[mt]);
            const float corr0 = ex2(m0[mt] - mn0);
            const float corr1 = ex2(m1[mt] - mn1);
            m0[mt] = mn0; m1[mt] = mn1;

            float sum0 = 0.0f, sum1 = 0.0f;
#pragma unroll
            for (int nt = 0; nt < 8; nt++) {
                s[mt][nt][0] = ex2(s[mt][nt][0] - mn0); sum0 += s[mt][nt][0];
                s[mt][nt][1] = ex2(s[mt][nt][1] - mn0); sum0 += s[mt][nt][1];
                s[mt][nt][2] = ex2(s[mt][nt][2] - mn1); sum1 += s[mt][nt][2];
                s[mt][nt][3] = ex2(s[mt][nt][3] - mn1); sum1 += s[mt][nt][3];
            }
            sum0 += __shfl_xor_sync(0xffffffffu, sum0, 1);
            sum0 += __shfl_xor_sync(0xffffffffu, sum0, 2);
            sum1 += __shfl_xor_sync(0xffffffffu, sum1, 1);
            sum1 += __shfl_xor_sync(0xffffffffu, sum1, 2);

            l0[mt] = l0[mt] * corr0 + sum0;
            l1[mt] = l1[mt] * corr1 + sum1;

            if (!__all_sync(0xffffffffu, keep)) {
#pragma unroll
                for (int nt = 0; nt < 8; nt++) {
                    oc[mt][nt][0] *= corr0; oc[mt][nt][1] *= corr0;
                    oc[mt][nt][2] *= corr1; oc[mt][nt][3] *= corr1;
                }
            }

            const int rp = mt * 16 + g;
#pragma unroll
            for (int nt = 0; nt < 8; nt++) {
                const int c = nt * 8 + 2 * tig;
                *reinterpret_cast<__half2*>(&Pw[rp * PSH + c]) =
                    __floats2half2_rn(s[mt][nt][0], s[mt][nt][1]);
                *reinterpret_cast<__half2*>(&Pw[(rp + 8) * PSH + c]) =
                    __floats2half2_rn(s[mt][nt][2], s[mt][nt][3]);
            }
        }
        __syncwarp();

        // O += P @ V : 4 k16 steps over 64 keys; V via ldmatrix.x4.trans
#pragma unroll
        for (int kk = 0; kk < 4; kk++) {
            unsigned pa[2][4];
#pragma unroll
            for (int mt = 0; mt < 2; mt++) {
                const int rp = mt * 16 + g;
                const int c = kk * 16 + 2 * tig;
                pa[mt][0] = *reinterpret_cast<const unsigned*>(&Pw[rp * PSH + c]);
                pa[mt][1] = *reinterpret_cast<const unsigned*>(&Pw[(rp + 8) * PSH + c]);
                pa[mt][2] = *reinterpret_cast<const unsigned*>(&Pw[rp * PSH + c + 8]);
                pa[mt][3] = *reinterpret_cast<const unsigned*>(&Pw[(rp + 8) * PSH + c + 8]);
            }
#pragma unroll
            for (int np = 0; np < 4; np++) {
                unsigned v0, v1, v2, v3;
                const unsigned va = sV + (unsigned)(((kk * 16 + vrow) * VSH
                                                     + np * 16 + vcol) * 2);
                ldmx4t(v0, v1, v2, v3, va);
#pragma unroll
                for (int mt = 0; mt < 2; mt++) {
                    mma16(oc[mt][np * 2],     pa[mt][0], pa[mt][1], pa[mt][2], pa[mt][3], v0, v1);
                    mma16(oc[mt][np * 2 + 1], pa[mt][0], pa[mt][1], pa[mt][2], pa[mt][3], v2, v3);
                }
            }
        }
        __syncthreads();   // all warps done reading Vs before restaging

        if (has_next) {
            stageV(t + 1);
            CP_COMMIT();
        }
        buf ^= 1;
    }

    // Normalize + write (half: consumed by proj GEMM)
#pragma unroll
    for (int mt = 0; mt < 2; mt++) {
        const float inv0 = 1.0f / l0[mt];
        const float inv1 = 1.0f / l1[mt];
        const size_t row = (size_t)b * L_ + qblk * 128 + wid * 32 + mt * 16 + g;
#pragma unroll
        for (int nt = 0; nt < 8; nt++) {
            const int c = h * HD_ + nt * 8 + 2 * tig;
            *reinterpret_cast<__half2*>(out + row * D_ + c) =
                __floats2half2_rn(oc[mt][nt][0] * inv0, oc[mt][nt][1] * inv0);
            *reinterpret_cast<__half2*>(out + (row + 8) * D_ + c) =
                __floats2half2_rn(oc[mt][nt][2] * inv1, oc[mt][nt][3] * inv1);
        }
    }
}

// ---------------------------------------------------------------------------
// Host launcher
// ---------------------------------------------------------------------------
extern "C" void kernel_launch(void* const* d_in, const int* in_sizes, int n_in,
                              void* d_out, int out_size)
{
    const float* x     = (const float*)d_in[0];
    const float* Wqkv  = (const float*)d_in[1];
    const float* bqkv  = (const float*)d_in[2];
    const float* Wproj = (const float*)d_in[3];
    const float* bproj = (const float*)d_in[4];
    float* out = (float*)d_out;

    __half *qkvh, *atth, *xh, *wqkvt, *wprojt;
    cudaGetSymbolAddress((void**)&qkvh,   g_qkvh);
    cudaGetSymbolAddress((void**)&atth,   g_atth);
    cudaGetSymbolAddress((void**)&xh,     g_xh);
    cudaGetSymbolAddress((void**)&wqkvt,  g_wqkvt);
    cudaGetSymbolAddress((void**)&wprojt, g_wprojt);

    static bool attr_set = false;
    if (!attr_set) {
        cudaFuncSetAttribute(attn_h,
                             cudaFuncAttributeMaxDynamicSharedMemorySize, ATT_SMEM);
        cudaFuncSetAttribute(gemm_h<true>,
                             cudaFuncAttributeMaxDynamicSharedMemorySize, GEMM_SMEM);
        cudaFuncSetAttribute(gemm_h<false>,
                             cudaFuncAttributeMaxDynamicSharedMemorySize, GEMM_SMEM);
        attr_set = true;
    }

    // 0) Convert inputs to half (weights transposed to [N][K])
    {
        int n4 = ML_ * D_ / 4;
        roundh_kernel<<<(n4 + 255) / 256, 256>>>(x, xh, n4);
        dim3 thr(32, 8);
        transpose_roundh_kernel<<<dim3(QKV_N / 32, D_ / 32), thr>>>(Wqkv, wqkvt, D_, QKV_N);
        transpose_roundh_kernel<<<dim3(D_ / 32, D_ / 32),   thr>>>(Wproj, wprojt, D_, D_);
    }

    // 1) QKV projection (half output)
    {
        dim3 grid(QKV_N / 128, ML_ / 128);
        gemm_h<true><<<grid, 128, GEMM_SMEM>>>(xh, wqkvt, bqkv, qkvh, ML_, QKV_N, D_);
    }
    // 2) Attention (half output)
    {
        dim3 grid(L_ / 128, H_, B_);
        attn_h<<<grid, ATT_WARPS * 32, ATT_SMEM>>>(qkvh, atth);
    }
    // 3) Output projection (fp32 output)
    {
        dim3 grid(D_ / 128, ML_ / 128);
        gemm_h<false><<<grid, 128, GEMM_SMEM>>>(atth, wprojt, bproj, out, ML_, D_, D_);
    }
}

// round 9
// speedup vs baseline: 7.3487x; 1.0768x over previous
#include <cuda_runtime.h>
#include <cuda_fp16.h>
#include <math.h>
#include <cstdint>

// Problem constants
#define B_   2
#define L_   2048
#define D_   768
#define H_   12
#define HD_  64
#define ML_  (B_ * L_)          // 4096
#define QKV_N (3 * D_)          // 2304
#define SCALE2_ 0.18033688011112042f   // 0.125 * log2(e)

// Scratch (device globals — no allocation allowed)
__device__ __half g_qkvh[(size_t)ML_ * QKV_N];
__device__ __half g_atth[(size_t)ML_ * D_];
__device__ __half g_xh[(size_t)ML_ * D_];
__device__ __half g_wqkvt[(size_t)QKV_N * D_];   // Wqkv^T [2304][768]
__device__ __half g_wprojt[(size_t)D_ * D_];     // Wproj^T [768][768]

// ---------------------------------------------------------------------------
// helpers
// ---------------------------------------------------------------------------
__device__ __forceinline__ float ex2(float x) {
    float y;
    asm("ex2.approx.ftz.f32 %0, %1;" : "=f"(y) : "f"(x));
    return y;
}

__device__ __forceinline__ void mma16(float* c,
                                      unsigned a0, unsigned a1, unsigned a2, unsigned a3,
                                      unsigned b0, unsigned b1) {
    asm volatile(
        "mma.sync.aligned.m16n8k16.row.col.f32.f16.f16.f32 "
        "{%0,%1,%2,%3},{%4,%5,%6,%7},{%8,%9},{%0,%1,%2,%3};"
        : "+f"(c[0]), "+f"(c[1]), "+f"(c[2]), "+f"(c[3])
        : "r"(a0), "r"(a1), "r"(a2), "r"(a3), "r"(b0), "r"(b1));
}

__device__ __forceinline__ void cpa16(unsigned dst, const void* src) {
    asm volatile("cp.async.cg.shared.global [%0], [%1], 16;\n" :: "r"(dst), "l"(src));
}
#define CP_COMMIT() asm volatile("cp.async.commit_group;\n" ::: "memory")
#define CP_WAIT(n)  asm volatile("cp.async.wait_group %0;\n" :: "n"(n) : "memory")

__device__ __forceinline__ void ldmx4(unsigned& r0, unsigned& r1,
                                      unsigned& r2, unsigned& r3, unsigned addr) {
    asm volatile("ldmatrix.sync.aligned.m8n8.x4.shared.b16 {%0,%1,%2,%3}, [%4];"
                 : "=r"(r0), "=r"(r1), "=r"(r2), "=r"(r3) : "r"(addr));
}
__device__ __forceinline__ void ldmx4t(unsigned& r0, unsigned& r1,
                                       unsigned& r2, unsigned& r3, unsigned addr) {
    asm volatile("ldmatrix.sync.aligned.m8n8.x4.trans.shared.b16 {%0,%1,%2,%3}, [%4];"
                 : "=r"(r0), "=r"(r1), "=r"(r2), "=r"(r3) : "r"(addr));
}

__device__ __forceinline__ unsigned pack_h2(float a, float b) {
    __half2 h = __floats2half2_rn(a, b);
    return *reinterpret_cast<unsigned*>(&h);
}

// ---------------------------------------------------------------------------
// Conversion prologue kernels
// ---------------------------------------------------------------------------
__global__ void roundh_kernel(const float* __restrict__ in,
                              __half* __restrict__ out, int n4)
{
    int i = blockIdx.x * blockDim.x + threadIdx.x;
    if (i < n4) {
        float4 v = reinterpret_cast<const float4*>(in)[i];
        *reinterpret_cast<__half2*>(out + (size_t)i * 4)     = __floats2half2_rn(v.x, v.y);
        *reinterpret_cast<__half2*>(out + (size_t)i * 4 + 2) = __floats2half2_rn(v.z, v.w);
    }
}

__global__ void transpose_roundh_kernel(const float* __restrict__ in,
                                        __half* __restrict__ out, int R, int C)
{
    __shared__ float tile[32][33];
    const int c = blockIdx.x * 32 + threadIdx.x;
    const int r = blockIdx.y * 32 + threadIdx.y;
#pragma unroll
    for (int i = 0; i < 32; i += 8)
        tile[threadIdx.y + i][threadIdx.x] = in[(size_t)(r + i) * C + c];
    __syncthreads();
    const int oc = blockIdx.y * 32 + threadIdx.x;
    const int orow = blockIdx.x * 32 + threadIdx.y;
#pragma unroll
    for (int i = 0; i < 32; i += 8)
        out[(size_t)(orow + i) * R + oc] = __float2half_rn(tile[threadIdx.x][threadIdx.y + i]);
}

// ---------------------------------------------------------------------------
// fp16 GEMM + bias: C[M,N] = A[M,K] @ Bt[N,K]^T + bias
// 128x128x64 tiles, 128 thr (4 warps 2x2), warp 64x64, mma m16n8k16,
// ldmatrix.x4 fragment loads, 2-stage cp.async, 2 CTAs/SM.
// ---------------------------------------------------------------------------
#define AS_ 72    // smem row stride in halves (64 data + 8 pad)
#define GEMM_SMEM (2 * (128 * AS_ + 128 * AS_) * 2)

template <bool HALF_OUT>
__global__ __launch_bounds__(128, 2)
void gemm_h(const __half* __restrict__ A, const __half* __restrict__ Bt,
            const float* __restrict__ bias, void* __restrict__ Cv,
            int M, int N, int K)
{
    extern __shared__ __half smh[];
    __half* As = smh;                      // [2][128][AS_]
    __half* Bs = smh + 2 * 128 * AS_;      // [2][128][AS_]

    const int tid  = threadIdx.x;
    const int wid  = tid >> 5;
    const int lane = tid & 31;
    const int g    = lane >> 2;
    const int tig  = lane & 3;
    const int wm   = wid >> 1;
    const int wn   = wid & 1;
    const int row0 = blockIdx.y * 128;
    const int col0 = blockIdx.x * 128;

    const unsigned sA = (unsigned)__cvta_generic_to_shared(As);
    const unsigned sB = (unsigned)__cvta_generic_to_shared(Bs);

    // ldmatrix per-lane offsets
    const int rowA = (lane & 7) + ((lane >> 3) & 1) * 8;  // A: m2/m3 are +8 col
    const int colA = (lane >> 4) * 8;
    const int rowB = (lane & 7) + ((lane >> 4) & 1) * 8;  // B: m1/m3 are +8 col
    const int colB = ((lane >> 3) & 1) * 8;

    float acc[4][8][4];
#pragma unroll
    for (int mt = 0; mt < 4; mt++)
#pragma unroll
        for (int nt = 0; nt < 8; nt++)
#pragma unroll
            for (int i = 0; i < 4; i++) acc[mt][nt][i] = 0.0f;

    const int T = K >> 6;   // 64 halves per stage

    auto stage = [&](int t, int buf) {
        const int k0 = t << 6;
#pragma unroll
        for (int i = 0; i < 8; i++) {       // A: 1024 chunks / 128 thr
            const int e = tid + i * 128;
            const int r = e >> 3, cc = (e & 7) * 8;
            cpa16(sA + (unsigned)((buf * 128 * AS_ + r * AS_ + cc) * 2),
                  A + (size_t)(row0 + r) * K + k0 + cc);
        }
#pragma unroll
        for (int i = 0; i < 8; i++) {       // B
            const int e = tid + i * 128;
            const int r = e >> 3, cc = (e & 7) * 8;
            cpa16(sB + (unsigned)((buf * 128 * AS_ + r * AS_ + cc) * 2),
                  Bt + (size_t)(col0 + r) * K + k0 + cc);
        }
    };

    stage(0, 0);
    CP_COMMIT();

    int buf = 0;
    for (int t = 0; t < T; t++) {
        if (t + 1 < T) {
            stage(t + 1, buf ^ 1);
            CP_COMMIT();
            CP_WAIT(1);
        } else {
            CP_WAIT(0);
        }
        __syncthreads();

        const unsigned sAb = sA + (unsigned)(buf * 128 * AS_ * 2);
        const unsigned sBb = sB + (unsigned)(buf * 128 * AS_ * 2);
#pragma unroll
        for (int kk = 0; kk < 4; kk++) {    // four k16 steps
            unsigned af[4][4], bf[4][4];
#pragma unroll
            for (int mt = 0; mt < 4; mt++)
                ldmx4(af[mt][0], af[mt][1], af[mt][2], af[mt][3],
                      sAb + (unsigned)(((wm * 64 + mt * 16 + rowA) * AS_
                                        + kk * 16 + colA) * 2));
#pragma unroll
            for (int j = 0; j < 4; j++)
                ldmx4(bf[j][0], bf[j][1], bf[j][2], bf[j][3],
                      sBb + (unsigned)(((wn * 64 + j * 16 + rowB) * AS_
                                        + kk * 16 + colB) * 2));
#pragma unroll
            for (int mt = 0; mt < 4; mt++)
#pragma unroll
                for (int j = 0; j < 4; j++) {
                    mma16(acc[mt][j * 2],     af[mt][0], af[mt][1], af[mt][2], af[mt][3],
                          bf[j][0], bf[j][1]);
                    mma16(acc[mt][j * 2 + 1], af[mt][0], af[mt][1], af[mt][2], af[mt][3],
                          bf[j][2], bf[j][3]);
                }
        }
        __syncthreads();
        buf ^= 1;
    }

    // Epilogue: bias + store
#pragma unroll
    for (int mt = 0; mt < 4; mt++) {
        const int r = row0 + wm * 64 + mt * 16 + g;
#pragma unroll
        for (int nt = 0; nt < 8; nt++) {
            const int c = col0 + wn * 64 + nt * 8 + tig * 2;
            const float b0v = bias[c], b1v = bias[c + 1];
            if (HALF_OUT) {
                __half* C = (__half*)Cv;
                *reinterpret_cast<__half2*>(C + (size_t)r * N + c) =
                    __floats2half2_rn(acc[mt][nt][0] + b0v, acc[mt][nt][1] + b1v);
                *reinterpret_cast<__half2*>(C + (size_t)(r + 8) * N + c) =
                    __floats2half2_rn(acc[mt][nt][2] + b0v, acc[mt][nt][3] + b1v);
            } else {
                float* C = (float*)Cv;
                *reinterpret_cast<float2*>(C + (size_t)r * N + c) =
                    make_float2(acc[mt][nt][0] + b0v, acc[mt][nt][1] + b1v);
                *reinterpret_cast<float2*>(C + (size_t)(r + 8) * N + c) =
                    make_float2(acc[mt][nt][2] + b0v, acc[mt][nt][3] + b1v);
            }
        }
    }
}

// ---------------------------------------------------------------------------
// Flash attention, fp16 MMA, exp2 softmax, ldmatrix fragment loads.
// CTA = (128 q-rows, head, batch), 4 warps x 32 q-rows.
// K double-buffered cp.async; V single-buffered (restaged after PV).
// ---------------------------------------------------------------------------
#define KSH 72
#define VSH 72
#define PSH 72
#define ATT_WARPS 4
#define ATT_SMEM ((2 * 64 * KSH + 64 * VSH + ATT_WARPS * 32 * PSH) * 2)

__global__ __launch_bounds__(ATT_WARPS * 32, 2)
void attn_h(const __half* __restrict__ qkv, __half* __restrict__ out)
{
    extern __shared__ __half smh[];
    __half* Ks = smh;                       // [2][64][KSH]
    __half* Vs = Ks + 2 * 64 * KSH;         // [64][VSH]
    __half* Ps = Vs + 64 * VSH;             // [4][32][PSH]

    const int tid  = threadIdx.x;
    const int wid  = tid >> 5;
    const int lane = tid & 31;
    const int g    = lane >> 2;
    const int tig  = lane & 3;
    const int qblk = blockIdx.x;
    const int h    = blockIdx.y;
    const int b    = blockIdx.z;

    const size_t rs    = QKV_N;
    const size_t baseQ = ((size_t)b * L_ + qblk * 128) * rs + h * HD_;
    const size_t baseK = (size_t)b * L_ * rs + D_ + h * HD_;
    const size_t baseV = (size_t)b * L_ * rs + 2 * D_ + h * HD_;

    const unsigned sK = (unsigned)__cvta_generic_to_shared(Ks);
    const unsigned sV = (unsigned)__cvta_generic_to_shared(Vs);
    const unsigned sP = (unsigned)__cvta_generic_to_shared(Ps)
                      + (unsigned)(wid * 32 * PSH * 2);

    // ldmatrix per-lane offsets
    const int rowA = (lane & 7) + ((lane >> 3) & 1) * 8;
    const int colA = (lane >> 4) * 8;
    const int rowB = (lane & 7) + ((lane >> 4) & 1) * 8;
    const int colB = ((lane >> 3) & 1) * 8;
    const int vrow = (lane & 7) + ((lane >> 3) & 1) * 8;   // trans load rows
    const int vcol = (lane >> 4) * 8;

    auto stageK = [&](int t, int buf) {
        const int j0 = t << 6;
#pragma unroll
        for (int i = 0; i < 4; i++) {
            const int e = tid + i * 128;
            const int r = e >> 3, cc = (e & 7) * 8;
            cpa16(sK + (unsigned)((buf * 64 * KSH + r * KSH + cc) * 2),
                  qkv + baseK + (size_t)(j0 + r) * rs + cc);
        }
    };
    auto stageV = [&](int t) {
        const int j0 = t << 6;
#pragma unroll
        for (int i = 0; i < 4; i++) {
            const int e = tid + i * 128;
            const int r = e >> 3, cc = (e & 7) * 8;
            cpa16(sV + (unsigned)((r * VSH + cc) * 2),
                  qkv + baseV + (size_t)(j0 + r) * rs + cc);
        }
    };

    stageK(0, 0); CP_COMMIT();
    stageV(0);    CP_COMMIT();

    // Q fragments: scaled by 0.125*log2e, half, register-resident
    unsigned qa[2][4][4];
#pragma unroll
    for (int mt = 0; mt < 2; mt++) {
        const __half* q0 = qkv + baseQ + (size_t)(wid * 32 + mt * 16 + g) * rs;
        const __half* q8 = q0 + 8 * rs;
#pragma unroll
        for (int kk = 0; kk < 4; kk++) {
            const int c = kk * 16 + 2 * tig;
#pragma unroll
            for (int p = 0; p < 2; p++) {
                float2 f0 = __half22float2(*reinterpret_cast<const __half2*>(q0 + c + p * 8));
                float2 f8 = __half22float2(*reinterpret_cast<const __half2*>(q8 + c + p * 8));
                qa[mt][kk][p * 2 + 0] = pack_h2(f0.x * SCALE2_, f0.y * SCALE2_);
                qa[mt][kk][p * 2 + 1] = pack_h2(f8.x * SCALE2_, f8.y * SCALE2_);
            }
        }
    }

    float oc[2][8][4];
#pragma unroll
    for (int mt = 0; mt < 2; mt++)
#pragma unroll
        for (int nt = 0; nt < 8; nt++)
#pragma unroll
            for (int i = 0; i < 4; i++) oc[mt][nt][i] = 0.0f;
    float m0[2] = {-INFINITY, -INFINITY}, m1[2] = {-INFINITY, -INFINITY};
    float l0[2] = {0.0f, 0.0f}, l1[2] = {0.0f, 0.0f};

    __half* Pw = Ps + wid * 32 * PSH;

    int buf = 0;
    const int T = L_ / 64;
    for (int t = 0; t < T; t++) {
        const bool has_next = (t + 1 < T);
        if (has_next) {
            stageK(t + 1, buf ^ 1);
            CP_COMMIT();
            CP_WAIT(1);
        } else {
            CP_WAIT(0);
        }
        __syncthreads();

        const unsigned sKb = sK + (unsigned)(buf * 64 * KSH * 2);

        // S2 = (Q*scale*log2e) @ K^T
        float s[2][8][4];
#pragma unroll
        for (int mt = 0; mt < 2; mt++)
#pragma unroll
            for (int nt = 0; nt < 8; nt++)
#pragma unroll
                for (int i = 0; i < 4; i++) s[mt][nt][i] = 0.0f;

#pragma unroll
        for (int kk = 0; kk < 4; kk++) {
            unsigned bf[4][4];
#pragma unroll
            for (int j = 0; j < 4; j++)
                ldmx4(bf[j][0], bf[j][1], bf[j][2], bf[j][3],
                      sKb + (unsigned)(((j * 16 + rowB) * KSH + kk * 16 + colB) * 2));
#pragma unroll
            for (int mt = 0; mt < 2; mt++)
#pragma unroll
                for (int j = 0; j < 4; j++) {
                    mma16(s[mt][j * 2],     qa[mt][kk][0], qa[mt][kk][1],
                          qa[mt][kk][2], qa[mt][kk][3], bf[j][0], bf[j][1]);
                    mma16(s[mt][j * 2 + 1], qa[mt][kk][0], qa[mt][kk][1],
                          qa[mt][kk][2], qa[mt][kk][3], bf[j][2], bf[j][3]);
                }
        }

        // Online softmax (exp2 domain) + P store (half)
#pragma unroll
        for (int mt = 0; mt < 2; mt++) {
            float mx0 = -INFINITY, mx1 = -INFINITY;
#pragma unroll
            for (int nt = 0; nt < 8; nt++) {
                mx0 = fmaxf(mx0, fmaxf(s[mt][nt][0], s[mt][nt][1]));
                mx1 = fmaxf(mx1, fmaxf(s[mt][nt][2], s[mt][nt][3]));
            }
            mx0 = fmaxf(mx0, __shfl_xor_sync(0xffffffffu, mx0, 1));
            mx0 = fmaxf(mx0, __shfl_xor_sync(0xffffffffu, mx0, 2));
            mx1 = fmaxf(mx1, __shfl_xor_sync(0xffffffffu, mx1, 1));
            mx1 = fmaxf(mx1, __shfl_xor_sync(0xffffffffu, mx1, 2));

            const float mn0 = fmaxf(m0[mt], mx0);
            const float mn1 = fmaxf(m1[mt], mx1);
            const bool keep = (mn0 == m0[mt]) && (mn1 == m1[mt]);
            const float corr0 = ex2(m0[mt] - mn0);
            const float corr1 = ex2(m1[mt] - mn1);
            m0[mt] = mn0; m1[mt] = mn1;

            float sum0 = 0.0f, sum1 = 0.0f;
#pragma unroll
            for (int nt = 0; nt < 8; nt++) {
                s[mt][nt][0] = ex2(s[mt][nt][0] - mn0); sum0 += s[mt][nt][0];
                s[mt][nt][1] = ex2(s[mt][nt][1] - mn0); sum0 += s[mt][nt][1];
                s[mt][nt][2] = ex2(s[mt][nt][2] - mn1); sum1 += s[mt][nt][2];
                s[mt][nt][3] = ex2(s[mt][nt][3] - mn1); sum1 += s[mt][nt][3];
            }
            sum0 += __shfl_xor_sync(0xffffffffu, sum0, 1);
            sum0 += __shfl_xor_sync(0xffffffffu, sum0, 2);
            sum1 += __shfl_xor_sync(0xffffffffu, sum1, 1);
            sum1 += __shfl_xor_sync(0xffffffffu, sum1, 2);

            l0[mt] = l0[mt] * corr0 + sum0;
            l1[mt] = l1[mt] * corr1 + sum1;

            if (!__all_sync(0xffffffffu, keep)) {
#pragma unroll
                for (int nt = 0; nt < 8; nt++) {
                    oc[mt][nt][0] *= corr0; oc[mt][nt][1] *= corr0;
                    oc[mt][nt][2] *= corr1; oc[mt][nt][3] *= corr1;
                }
            }

            const int rp = mt * 16 + g;
#pragma unroll
            for (int nt = 0; nt < 8; nt++) {
                const int c = nt * 8 + 2 * tig;
                *reinterpret_cast<__half2*>(&Pw[rp * PSH + c]) =
                    __floats2half2_rn(s[mt][nt][0], s[mt][nt][1]);
                *reinterpret_cast<__half2*>(&Pw[(rp + 8) * PSH + c]) =
                    __floats2half2_rn(s[mt][nt][2], s[mt][nt][3]);
            }
        }
        __syncwarp();

        // O += P @ V : P via ldmatrix.x4, V via ldmatrix.x4.trans
#pragma unroll
        for (int kk = 0; kk < 4; kk++) {
            unsigned pa[2][4];
#pragma unroll
            for (int mt = 0; mt < 2; mt++)
                ldmx4(pa[mt][0], pa[mt][1], pa[mt][2], pa[mt][3],
                      sP + (unsigned)(((mt * 16 + rowA) * PSH + kk * 16 + colA) * 2));
#pragma unroll
            for (int np = 0; np < 4; np++) {
                unsigned v0, v1, v2, v3;
                const unsigned va = sV + (unsigned)(((kk * 16 + vrow) * VSH
                                                     + np * 16 + vcol) * 2);
                ldmx4t(v0, v1, v2, v3, va);
#pragma unroll
                for (int mt = 0; mt < 2; mt++) {
                    mma16(oc[mt][np * 2],     pa[mt][0], pa[mt][1], pa[mt][2], pa[mt][3], v0, v1);
                    mma16(oc[mt][np * 2 + 1], pa[mt][0], pa[mt][1], pa[mt][2], pa[mt][3], v2, v3);
                }
            }
        }
        __syncthreads();

        if (has_next) {
            stageV(t + 1);
            CP_COMMIT();
        }
        buf ^= 1;
    }

    // Normalize + write (half)
#pragma unroll
    for (int mt = 0; mt < 2; mt++) {
        const float inv0 = 1.0f / l0[mt];
        const float inv1 = 1.0f / l1[mt];
        const size_t row = (size_t)b * L_ + qblk * 128 + wid * 32 + mt * 16 + g;
#pragma unroll
        for (int nt = 0; nt < 8; nt++) {
            const int c = h * HD_ + nt * 8 + 2 * tig;
            *reinterpret_cast<__half2*>(out + row * D_ + c) =
                __floats2half2_rn(oc[mt][nt][0] * inv0, oc[mt][nt][1] * inv0);
            *reinterpret_cast<__half2*>(out + (row + 8) * D_ + c) =
                __floats2half2_rn(oc[mt][nt][2] * inv1, oc[mt][nt][3] * inv1);
        }
    }
}

// ---------------------------------------------------------------------------
// Host launcher
// ---------------------------------------------------------------------------
extern "C" void kernel_launch(void* const* d_in, const int* in_sizes, int n_in,
                              void* d_out, int out_size)
{
    const float* x     = (const float*)d_in[0];
    const float* Wqkv  = (const float*)d_in[1];
    const float* bqkv  = (const float*)d_in[2];
    const float* Wproj = (const float*)d_in[3];
    const float* bproj = (const float*)d_in[4];
    float* out = (float*)d_out;

    __half *qkvh, *atth, *xh, *wqkvt, *wprojt;
    cudaGetSymbolAddress((void**)&qkvh,   g_qkvh);
    cudaGetSymbolAddress((void**)&atth,   g_atth);
    cudaGetSymbolAddress((void**)&xh,     g_xh);
    cudaGetSymbolAddress((void**)&wqkvt,  g_wqkvt);
    cudaGetSymbolAddress((void**)&wprojt, g_wprojt);

    static bool attr_set = false;
    if (!attr_set) {
        cudaFuncSetAttribute(attn_h,
                             cudaFuncAttributeMaxDynamicSharedMemorySize, ATT_SMEM);
        cudaFuncSetAttribute(gemm_h<true>,
                             cudaFuncAttributeMaxDynamicSharedMemorySize, GEMM_SMEM);
        cudaFuncSetAttribute(gemm_h<false>,
                             cudaFuncAttributeMaxDynamicSharedMemorySize, GEMM_SMEM);
        attr_set = true;
    }

    // 0) Convert inputs to half (weights transposed to [N][K])
    {
        int n4 = ML_ * D_ / 4;
        roundh_kernel<<<(n4 + 255) / 256, 256>>>(x, xh, n4);
        dim3 thr(32, 8);
        transpose_roundh_kernel<<<dim3(QKV_N / 32, D_ / 32), thr>>>(Wqkv, wqkvt, D_, QKV_N);
        transpose_roundh_kernel<<<dim3(D_ / 32, D_ / 32),   thr>>>(Wproj, wprojt, D_, D_);
    }

    // 1) QKV projection (half output)
    {
        dim3 grid(QKV_N / 128, ML_ / 128);
        gemm_h<true><<<grid, 128, GEMM_SMEM>>>(xh, wqkvt, bqkv, qkvh, ML_, QKV_N, D_);
    }
    // 2) Attention (half output)
    {
        dim3 grid(L_ / 128, H_, B_);
        attn_h<<<grid, ATT_WARPS * 32, ATT_SMEM>>>(qkvh, atth);
    }
    // 3) Output projection (fp32 output)
    {
        dim3 grid(D_ / 128, ML_ / 128);
        gemm_h<false><<<grid, 128, GEMM_SMEM>>>(atth, wprojt, bproj, out, ML_, D_, D_);
    }
}